// round 3
// baseline (speedup 1.0000x reference)
#include <cuda_runtime.h>

#define BB   16
#define CIN  512
#define COUT 512
#define HH   64
#define WW   64
#define SS   512

#define IC_CHUNK 8
#define WPAD 66           // row stride (floats) for weight smem: even (8B align) + conflict-light

// scratch (device globals: no allocation allowed)
__device__ float g_smod[BB * CIN];     // modulation s[b][i]
__device__ float g_demod[BB * COUT];   // demod[b][o]
__device__ float g_wsq[COUT * CIN];    // sum over 3x3 of weight^2

// ---------------- kernel 1: s = style @ mod_w^T + mod_b (warp per output) ----------------
__global__ void k_mod(const float* __restrict__ style, const float* __restrict__ mod_w,
                      const float* __restrict__ mod_b) {
    int wid  = (blockIdx.x * blockDim.x + threadIdx.x) >> 5;
    int lane = threadIdx.x & 31;
    if (wid >= BB * CIN) return;
    int b = wid >> 9, i = wid & 511;
    const float* st = style + b * SS;
    const float* mw = mod_w + (size_t)i * SS;
    float sum = 0.f;
    for (int l = lane; l < SS; l += 32) sum += st[l] * mw[l];
    #pragma unroll
    for (int o = 16; o > 0; o >>= 1) sum += __shfl_xor_sync(0xffffffffu, sum, o);
    if (lane == 0) g_smod[wid] = sum + mod_b[i];
}

// ---------------- kernel 2: wsq[o*CIN+i] = sum_t weight[o,i,t]^2 ----------------
__global__ void k_wsq(const float* __restrict__ weight) {
    int idx = blockIdx.x * blockDim.x + threadIdx.x;
    if (idx >= COUT * CIN) return;
    const float* w = weight + (size_t)idx * 9;
    float s = 0.f;
    #pragma unroll
    for (int t = 0; t < 9; ++t) s += w[t] * w[t];
    g_wsq[idx] = s;
}

// ---------------- kernel 3: demod[b][o] = rsqrt(scale^2 * sum_i wsq[o,i]*s[b,i]^2 + eps) ----
__global__ void k_demod() {
    int wid  = (blockIdx.x * blockDim.x + threadIdx.x) >> 5;
    int lane = threadIdx.x & 31;
    if (wid >= BB * COUT) return;
    int b = wid >> 9, o = wid & 511;
    const float* wsq = g_wsq + (size_t)o * CIN;
    const float* sm  = g_smod + b * CIN;
    float sum = 0.f;
    for (int i = lane; i < CIN; i += 32) { float s = sm[i]; sum += wsq[i] * s * s; }
    #pragma unroll
    for (int off = 16; off > 0; off >>= 1) sum += __shfl_xor_sync(0xffffffffu, sum, off);
    const float scale2 = 2.1701389e-4f;  // 1/(Cin*K*K) = 1/4608
    if (lane == 0) g_demod[wid] = rsqrtf(scale2 * sum + 1e-8f);
}

// ---------------- kernel 4: modulated conv, implicit GEMM, fp32x2 FMA ----------------
// Block: 256 threads -> 64 output channels x 64 pixels (8x8 spatial tile), one batch.
// Inner math uses fma.rn.f32x2 (packed pairs over output channels) for 2x fp32 rate.
__global__ void __launch_bounds__(256, 3)
k_conv(const float* __restrict__ input, const float* __restrict__ weight,
       float* __restrict__ out) {
    __shared__ __align__(16) float wsh[72 * WPAD];          // [ic*9+t][oc], scaled weights
    __shared__ __align__(16) float ish[IC_CHUNK * 100];     // [ic][10][10] padded patch

    const int b       = blockIdx.z;
    const int oc_base = blockIdx.y * 64;
    const int tile    = blockIdx.x;            // 0..63
    const int tr = (tile >> 3) * 8;            // spatial tile origin
    const int tc = (tile & 7) * 8;

    const int tid = threadIdx.x;
    const int tx = tid & 15, ty = tid >> 4;
    const int R  = tx >> 1;                    // row within 8x8 tile
    const int C0 = (tx & 1) * 4;               // col base (4 consecutive pixels, same row)
    const int oc0 = ty * 4;                    // 4 consecutive output channels

    // acc[p][jj]: packed f32x2 (oc0+2jj, oc0+2jj+1) for pixel p
    unsigned long long acc[4][2];
    #pragma unroll
    for (int p = 0; p < 4; ++p) { acc[p][0] = 0ull; acc[p][1] = 0ull; }

    const float scale = 0.014731391f;          // 1/sqrt(4608)
    const float* smod = g_smod + b * CIN;
    const float* dmod = g_demod + b * COUT + oc_base;

    for (int ic_base = 0; ic_base < CIN; ic_base += IC_CHUNK) {
        // stage scaled weights: 64 oc x 8 ic x 9 taps
        #pragma unroll 3
        for (int i = tid; i < 64 * 72; i += 256) {
            int oc  = i / 72;
            int rem = i - oc * 72;
            int ic  = rem / 9;
            int tt  = rem - ic * 9;
            float w = weight[(size_t)(oc_base + oc) * (CIN * 9) + (ic_base + ic) * 9 + tt];
            wsh[rem * WPAD + oc] = w * (scale * smod[ic_base + ic] * dmod[oc]);
        }
        // stage input patch: 8 ch x 10x10 (zero-padded halo)
        #pragma unroll 2
        for (int i = tid; i < IC_CHUNK * 100; i += 256) {
            int ic = i / 100;
            int r2 = i - ic * 100;
            int rr = r2 / 10;
            int cc = r2 - rr * 10;
            int gr = tr + rr - 1, gc = tc + cc - 1;
            float v = 0.f;
            if (gr >= 0 && gr < HH && gc >= 0 && gc < WW)
                v = input[((size_t)(b * CIN + ic_base + ic) * HH + gr) * WW + gc];
            ish[i] = v;
        }
        __syncthreads();

        #pragma unroll
        for (int ic = 0; ic < IC_CHUNK; ++ic) {
            // stage 3x6 input window for this thread's 4 pixels into registers
            const float* ip = ish + ic * 100 + R * 10 + C0;
            float rowv[3][6];
            #pragma unroll
            for (int r = 0; r < 3; ++r)
                #pragma unroll
                for (int c = 0; c < 6; ++c)
                    rowv[r][c] = ip[r * 10 + c];

            const float* wp = wsh + ic * 9 * WPAD + oc0;
            #pragma unroll
            for (int t = 0; t < 9; ++t) {
                const int kh = t / 3, kw = t - kh * 3;
                unsigned long long w01 = *(const unsigned long long*)(wp + t * WPAD);
                unsigned long long w23 = *(const unsigned long long*)(wp + t * WPAD + 2);
                #pragma unroll
                for (int p = 0; p < 4; ++p) {
                    unsigned long long iv2;
                    asm("mov.b64 %0, {%1, %1};" : "=l"(iv2) : "f"(rowv[kh][kw + p]));
                    asm("fma.rn.f32x2 %0, %1, %2, %0;" : "+l"(acc[p][0]) : "l"(w01), "l"(iv2));
                    asm("fma.rn.f32x2 %0, %1, %2, %0;" : "+l"(acc[p][1]) : "l"(w23), "l"(iv2));
                }
            }
        }
        __syncthreads();
    }

    // epilogue: 4 oc x 4 px per thread; the 4 pixels are contiguous in one row -> STG.128
    const int gr = tr + R, gc = tc + C0;
    #pragma unroll
    for (int j = 0; j < 4; ++j) {
        const int oc = oc_base + oc0 + j;
        float4 v;
        float* vp = (float*)&v;
        #pragma unroll
        for (int p = 0; p < 4; ++p) {
            uint2 u = *(uint2*)&acc[p][j >> 1];
            vp[p] = __uint_as_float((j & 1) ? u.y : u.x);
        }
        *(float4*)(out + (((size_t)b * COUT + oc) * HH + gr) * WW + gc) = v;
    }
}

// ---------------- launch ----------------
extern "C" void kernel_launch(void* const* d_in, const int* in_sizes, int n_in,
                              void* d_out, int out_size) {
    const float* input  = (const float*)d_in[0];  // (16,512,64,64)
    const float* style  = (const float*)d_in[1];  // (16,512)
    const float* weight = (const float*)d_in[2];  // (512,512,3,3)
    const float* mod_w  = (const float*)d_in[3];  // (512,512)
    const float* mod_b  = (const float*)d_in[4];  // (512,)
    float* out = (float*)d_out;                   // (16,512,64,64)
    (void)in_sizes; (void)n_in; (void)out_size;

    // 1) modulation (warp per (b,i)): 8192 warps
    k_mod<<<1024, 256>>>(style, mod_w, mod_b);
    // 2) per-(o,i) weight energy
    k_wsq<<<(COUT * CIN + 255) / 256, 256>>>(weight);
    // 3) demod (warp per (b,o)): 8192 warps
    k_demod<<<1024, 256>>>();
    // 4) modulated conv
    dim3 grid(64 /*spatial tiles*/, COUT / 64, BB);
    k_conv<<<grid, 256>>>(input, weight, out);
}

// round 4
// speedup vs baseline: 1.0026x; 1.0026x over previous
#include <cuda_runtime.h>

#define BB   16
#define CIN  512
#define COUT 512
#define HH   64
#define WW   64
#define SS   512

#define IC_CHUNK 8
#define WPAD 66           // row stride (floats) for weight smem: even (8B align) + conflict-light

// scratch (device globals: no allocation allowed)
__device__ float g_smod[BB * CIN];     // modulation s[b][i]
__device__ float g_demod[BB * COUT];   // demod[b][o]
__device__ float g_wsq[COUT * CIN];    // sum over 3x3 of weight^2

// ---------------- kernel 1: s = style @ mod_w^T + mod_b (warp per output) ----------------
__global__ void k_mod(const float* __restrict__ style, const float* __restrict__ mod_w,
                      const float* __restrict__ mod_b) {
    int wid  = (blockIdx.x * blockDim.x + threadIdx.x) >> 5;
    int lane = threadIdx.x & 31;
    if (wid >= BB * CIN) return;
    int b = wid >> 9, i = wid & 511;
    const float* st = style + b * SS;
    const float* mw = mod_w + (size_t)i * SS;
    float sum = 0.f;
    for (int l = lane; l < SS; l += 32) sum += st[l] * mw[l];
    #pragma unroll
    for (int o = 16; o > 0; o >>= 1) sum += __shfl_xor_sync(0xffffffffu, sum, o);
    if (lane == 0) g_smod[wid] = sum + mod_b[i];
}

// ---------------- kernel 2: wsq[o*CIN+i] = sum_t weight[o,i,t]^2 ----------------
__global__ void k_wsq(const float* __restrict__ weight) {
    int idx = blockIdx.x * blockDim.x + threadIdx.x;
    if (idx >= COUT * CIN) return;
    const float* w = weight + (size_t)idx * 9;
    float s = 0.f;
    #pragma unroll
    for (int t = 0; t < 9; ++t) s += w[t] * w[t];
    g_wsq[idx] = s;
}

// ---------------- kernel 3: demod[b][o] = rsqrt(scale^2 * sum_i wsq[o,i]*s[b,i]^2 + eps) ----
__global__ void k_demod() {
    int wid  = (blockIdx.x * blockDim.x + threadIdx.x) >> 5;
    int lane = threadIdx.x & 31;
    if (wid >= BB * COUT) return;
    int b = wid >> 9, o = wid & 511;
    const float* wsq = g_wsq + (size_t)o * CIN;
    const float* sm  = g_smod + b * CIN;
    float sum = 0.f;
    for (int i = lane; i < CIN; i += 32) { float s = sm[i]; sum += wsq[i] * s * s; }
    #pragma unroll
    for (int off = 16; off > 0; off >>= 1) sum += __shfl_xor_sync(0xffffffffu, sum, off);
    const float scale2 = 2.1701389e-4f;  // 1/(Cin*K*K) = 1/4608
    if (lane == 0) g_demod[wid] = rsqrtf(scale2 * sum + 1e-8f);
}

// ---------------- kernel 4: modulated conv, implicit GEMM, fp32x2 FMA ----------------
// Block: 256 threads -> 64 output channels x 64 pixels (8x8 spatial tile), one batch.
// Inner math uses fma.rn.f32x2 (packed pairs over output channels) for 2x fp32 rate.
__global__ void __launch_bounds__(256, 3)
k_conv(const float* __restrict__ input, const float* __restrict__ weight,
       float* __restrict__ out) {
    __shared__ __align__(16) float wsh[72 * WPAD];          // [ic*9+t][oc], scaled weights
    __shared__ __align__(16) float ish[IC_CHUNK * 100];     // [ic][10][10] padded patch

    const int b       = blockIdx.z;
    const int oc_base = blockIdx.y * 64;
    const int tile    = blockIdx.x;            // 0..63
    const int tr = (tile >> 3) * 8;            // spatial tile origin
    const int tc = (tile & 7) * 8;

    const int tid = threadIdx.x;
    const int tx = tid & 15, ty = tid >> 4;
    const int R  = tx >> 1;                    // row within 8x8 tile
    const int C0 = (tx & 1) * 4;               // col base (4 consecutive pixels, same row)
    const int oc0 = ty * 4;                    // 4 consecutive output channels

    // acc[p][jj]: packed f32x2 (oc0+2jj, oc0+2jj+1) for pixel p
    unsigned long long acc[4][2];
    #pragma unroll
    for (int p = 0; p < 4; ++p) { acc[p][0] = 0ull; acc[p][1] = 0ull; }

    const float scale = 0.014731391f;          // 1/sqrt(4608)
    const float* smod = g_smod + b * CIN;
    const float* dmod = g_demod + b * COUT + oc_base;

    for (int ic_base = 0; ic_base < CIN; ic_base += IC_CHUNK) {
        // stage scaled weights: 64 oc x 8 ic x 9 taps
        #pragma unroll 3
        for (int i = tid; i < 64 * 72; i += 256) {
            int oc  = i / 72;
            int rem = i - oc * 72;
            int ic  = rem / 9;
            int tt  = rem - ic * 9;
            float w = weight[(size_t)(oc_base + oc) * (CIN * 9) + (ic_base + ic) * 9 + tt];
            wsh[rem * WPAD + oc] = w * (scale * smod[ic_base + ic] * dmod[oc]);
        }
        // stage input patch: 8 ch x 10x10 (zero-padded halo)
        #pragma unroll 2
        for (int i = tid; i < IC_CHUNK * 100; i += 256) {
            int ic = i / 100;
            int r2 = i - ic * 100;
            int rr = r2 / 10;
            int cc = r2 - rr * 10;
            int gr = tr + rr - 1, gc = tc + cc - 1;
            float v = 0.f;
            if (gr >= 0 && gr < HH && gc >= 0 && gc < WW)
                v = input[((size_t)(b * CIN + ic_base + ic) * HH + gr) * WW + gc];
            ish[i] = v;
        }
        __syncthreads();

        #pragma unroll
        for (int ic = 0; ic < IC_CHUNK; ++ic) {
            // stage 3x6 input window for this thread's 4 pixels into registers
            const float* ip = ish + ic * 100 + R * 10 + C0;
            float rowv[3][6];
            #pragma unroll
            for (int r = 0; r < 3; ++r)
                #pragma unroll
                for (int c = 0; c < 6; ++c)
                    rowv[r][c] = ip[r * 10 + c];

            const float* wp = wsh + ic * 9 * WPAD + oc0;
            #pragma unroll
            for (int t = 0; t < 9; ++t) {
                const int kh = t / 3, kw = t - kh * 3;
                unsigned long long w01 = *(const unsigned long long*)(wp + t * WPAD);
                unsigned long long w23 = *(const unsigned long long*)(wp + t * WPAD + 2);
                #pragma unroll
                for (int p = 0; p < 4; ++p) {
                    unsigned long long iv2;
                    asm("mov.b64 %0, {%1, %1};" : "=l"(iv2) : "f"(rowv[kh][kw + p]));
                    asm("fma.rn.f32x2 %0, %1, %2, %0;" : "+l"(acc[p][0]) : "l"(w01), "l"(iv2));
                    asm("fma.rn.f32x2 %0, %1, %2, %0;" : "+l"(acc[p][1]) : "l"(w23), "l"(iv2));
                }
            }
        }
        __syncthreads();
    }

    // epilogue: 4 oc x 4 px per thread; the 4 pixels are contiguous in one row -> STG.128
    const int gr = tr + R, gc = tc + C0;
    #pragma unroll
    for (int j = 0; j < 4; ++j) {
        const int oc = oc_base + oc0 + j;
        float4 v;
        float* vp = (float*)&v;
        #pragma unroll
        for (int p = 0; p < 4; ++p) {
            uint2 u = *(uint2*)&acc[p][j >> 1];
            vp[p] = __uint_as_float((j & 1) ? u.y : u.x);
        }
        *(float4*)(out + (((size_t)b * COUT + oc) * HH + gr) * WW + gc) = v;
    }
}

// ---------------- launch ----------------
extern "C" void kernel_launch(void* const* d_in, const int* in_sizes, int n_in,
                              void* d_out, int out_size) {
    const float* input  = (const float*)d_in[0];  // (16,512,64,64)
    const float* style  = (const float*)d_in[1];  // (16,512)
    const float* weight = (const float*)d_in[2];  // (512,512,3,3)
    const float* mod_w  = (const float*)d_in[3];  // (512,512)
    const float* mod_b  = (const float*)d_in[4];  // (512,)
    float* out = (float*)d_out;                   // (16,512,64,64)
    (void)in_sizes; (void)n_in; (void)out_size;

    // 1) modulation (warp per (b,i)): 8192 warps
    k_mod<<<1024, 256>>>(style, mod_w, mod_b);
    // 2) per-(o,i) weight energy
    k_wsq<<<(COUT * CIN + 255) / 256, 256>>>(weight);
    // 3) demod (warp per (b,o)): 8192 warps
    k_demod<<<1024, 256>>>();
    // 4) modulated conv
    dim3 grid(64 /*spatial tiles*/, COUT / 64, BB);
    k_conv<<<grid, 256>>>(input, weight, out);
}

// round 7
// speedup vs baseline: 4.3131x; 4.3017x over previous
#include <cuda_runtime.h>
#include <cuda_bf16.h>
#include <cstdint>

#define BB   16
#define CIN  512
#define COUT 512
#define HH   64
#define WW   64
#define SS   512

// ---------------- scratch (__device__ globals: allocation-free) ----------------
__device__ float g_smod[BB * CIN];      // s[b][i]
__device__ float g_demod[BB * COUT];    // demod[b][o]
__device__ float g_wsq[COUT * CIN];     // per-(o,i) 3x3 weight energy

// split weights, [t][oc][ic], bf16 hi/lo
__device__ __align__(16) unsigned short g_wph[9 * COUT * CIN];
__device__ __align__(16) unsigned short g_wpl[9 * COUT * CIN];
// padded modulated input, channel-last [b][66][66][ic], bf16 hi/lo
__device__ __align__(16) unsigned short g_xph[35684352];
__device__ __align__(16) unsigned short g_xpl[35684352];

// ---------------- baseline-ISA helpers (sm_80-era: safe at .target sm_103) ----
__device__ __forceinline__ void cp16(uint32_t dst, const void* src) {
    asm volatile("cp.async.cg.shared.global [%0], [%1], 16;" :: "r"(dst), "l"(src) : "memory");
}
__device__ __forceinline__ void cp_commit() { asm volatile("cp.async.commit_group;" ::: "memory"); }
template <int N> __device__ __forceinline__ void cp_wait() {
    asm volatile("cp.async.wait_group %0;" :: "n"(N) : "memory");
}
#define LDSM4(r, addr) \
    asm volatile("ldmatrix.sync.aligned.m8n8.x4.shared.b16 {%0,%1,%2,%3}, [%4];" \
                 : "=r"((r)[0]), "=r"((r)[1]), "=r"((r)[2]), "=r"((r)[3]) : "r"(addr))
#define MMA(c, a, b0v, b1v) \
    asm volatile("mma.sync.aligned.m16n8k16.row.col.f32.bf16.bf16.f32 " \
                 "{%0,%1,%2,%3}, {%4,%5,%6,%7}, {%8,%9}, {%0,%1,%2,%3};" \
                 : "+f"((c)[0]), "+f"((c)[1]), "+f"((c)[2]), "+f"((c)[3]) \
                 : "r"((a)[0]), "r"((a)[1]), "r"((a)[2]), "r"((a)[3]), "r"(b0v), "r"(b1v))

// ---------------- kernel 1: s = style @ mod_w^T + mod_b ----------------
__global__ void k_mod(const float* __restrict__ style, const float* __restrict__ mod_w,
                      const float* __restrict__ mod_b) {
    int wid  = (blockIdx.x * blockDim.x + threadIdx.x) >> 5;
    int lane = threadIdx.x & 31;
    if (wid >= BB * CIN) return;
    int b = wid >> 9, i = wid & 511;
    const float* st = style + b * SS;
    const float* mw = mod_w + (size_t)i * SS;
    float sum = 0.f;
    for (int l = lane; l < SS; l += 32) sum += st[l] * mw[l];
    #pragma unroll
    for (int o = 16; o > 0; o >>= 1) sum += __shfl_xor_sync(0xffffffffu, sum, o);
    if (lane == 0) g_smod[wid] = sum + mod_b[i];
}

// ---------------- kernel 2: wsq ----------------
__global__ void k_wsq(const float* __restrict__ weight) {
    int idx = blockIdx.x * blockDim.x + threadIdx.x;
    if (idx >= COUT * CIN) return;
    const float* w = weight + (size_t)idx * 9;
    float s = 0.f;
    #pragma unroll
    for (int t = 0; t < 9; ++t) s += w[t] * w[t];
    g_wsq[idx] = s;
}

// ---------------- kernel 3: demod ----------------
__global__ void k_demod() {
    int wid  = (blockIdx.x * blockDim.x + threadIdx.x) >> 5;
    int lane = threadIdx.x & 31;
    if (wid >= BB * COUT) return;
    int b = wid >> 9, o = wid & 511;
    const float* wsq = g_wsq + (size_t)o * CIN;
    const float* sm  = g_smod + b * CIN;
    float sum = 0.f;
    for (int i = lane; i < CIN; i += 32) { float s = sm[i]; sum += wsq[i] * s * s; }
    #pragma unroll
    for (int off = 16; off > 0; off >>= 1) sum += __shfl_xor_sync(0xffffffffu, sum, off);
    const float scale2 = 2.1701389e-4f;   // 1/(Cin*K*K)
    if (lane == 0) g_demod[wid] = rsqrtf(scale2 * sum + 1e-8f);
}

// ---------------- kernel 4: split weights -> [t][oc][ic] bf16 hi/lo ----------------
__global__ void k_wprep(const float* __restrict__ weight) {
    int idx = blockIdx.x * 256 + threadIdx.x;
    if (idx >= COUT * CIN) return;
    int oc = idx >> 9, ic = idx & 511;
    const float* w = weight + (size_t)idx * 9;
    #pragma unroll
    for (int t = 0; t < 9; ++t) {
        float x = w[t];
        __nv_bfloat16 h = __float2bfloat16_rn(x);
        float hf = __bfloat162float(h);
        __nv_bfloat16 l = __float2bfloat16_rn(x - hf);
        size_t o = ((size_t)t * COUT + oc) * CIN + ic;
        g_wph[o] = __bfloat16_as_ushort(h);
        g_wpl[o] = __bfloat16_as_ushort(l);
    }
}

// ---------------- kernel 5: zero pad border of xprep ----------------
__global__ void k_border() {
    int idx = blockIdx.x * 256 + threadIdx.x;   // b*4356 + rr*66 + cc
    if (idx >= BB * 66 * 66) return;
    int cell = idx % 4356;
    int rr = cell / 66, cc = cell % 66;
    if (rr == 0 || rr == 65 || cc == 0 || cc == 65) {
        size_t o = (size_t)idx * 512;
        uint4 z = make_uint4(0, 0, 0, 0);
        #pragma unroll
        for (int k = 0; k < 64; ++k) {
            *(uint4*)(g_xph + o + k * 8) = z;
            *(uint4*)(g_xpl + o + k * 8) = z;
        }
    }
}

// ---------------- kernel 6: modulate + split + transpose input -> xprep ----------------
__global__ void __launch_bounds__(256)
k_xprep(const float* __restrict__ input) {
    __shared__ __align__(16) unsigned short sh[64 * 128];
    __shared__ __align__(16) unsigned short sl[64 * 128];
    const int r = blockIdx.x, b = blockIdx.y, tid = threadIdx.x;
    const float scale = 0.014731391f;   // 1/sqrt(4608)
    for (int icb = 0; icb < CIN; icb += 128) {
        #pragma unroll
        for (int k = 0; k < 8; ++k) {
            int idx = tid + (k << 8);
            int icl = idx >> 4, c4 = idx & 15;
            int ic  = icb + icl;
            float s = scale * g_smod[b * CIN + ic];
            float4 v = *(const float4*)(input + ((size_t)(b * CIN + ic) * HH + r) * WW + (c4 << 2));
            float xs[4] = {v.x * s, v.y * s, v.z * s, v.w * s};
            #pragma unroll
            for (int j = 0; j < 4; ++j) {
                __nv_bfloat16 h = __float2bfloat16_rn(xs[j]);
                float hf = __bfloat162float(h);
                __nv_bfloat16 l = __float2bfloat16_rn(xs[j] - hf);
                int c = (c4 << 2) + j;
                sh[c * 128 + icl] = __bfloat16_as_ushort(h);
                sl[c * 128 + icl] = __bfloat16_as_ushort(l);
            }
        }
        __syncthreads();
        #pragma unroll
        for (int k = 0; k < 4; ++k) {
            int q = tid + (k << 8);
            int c = q >> 4, kk = q & 15;
            size_t dst = (((size_t)b * 66 + r + 1) * 66 + c + 1) * 512 + icb + (kk << 3);
            *(uint4*)(g_xph + dst) = *(const uint4*)(sh + c * 128 + (kk << 3));
            *(uint4*)(g_xpl + dst) = *(const uint4*)(sl + c * 128 + (kk << 3));
        }
        __syncthreads();
    }
}

// ---------------- kernel 7: warp-MMA implicit-GEMM conv (bf16 split) ----------------
// CTA: M=128 oc x N=128 px (2 rows). 8 warps (2x4), warp tile 64x32.
// K: 9 taps x 8 ic-chunks of 64; per k16 step 3 MMAs (wh*xh + wl*xh + wh*xl).
// Double-buffered cp.async staging, SW128-style XOR swizzle, conflict-free ldmatrix.
__global__ void __launch_bounds__(256, 1)
k_conv_mma(float* __restrict__ out) {
    extern __shared__ char dsm[];
    const int tid = threadIdx.x, lane = tid & 31, wid = tid >> 5;
    const int wm = wid >> 2, wn = wid & 3;
    const int b = blockIdx.z, ocb = blockIdx.y << 7, rp = blockIdx.x;  // rp: row-pair 0..31

    const uint32_t sb = (uint32_t)__cvta_generic_to_shared(dsm);
    const unsigned short* __restrict__ xbh = g_xph + (size_t)b * 66 * 66 * 512;
    const unsigned short* __restrict__ xbl = g_xpl + (size_t)b * 66 * 66 * 512;

    // staging coords (per thread, fixed)
    const int srow = tid >> 3, scc = tid & 7;          // within-q base; q = tid + k*256
    (void)srow; (void)scc;

    // ldmatrix row offsets (fixed per thread)
    uint32_t arow_off[4], brow_off[2];
    #pragma unroll
    for (int mi = 0; mi < 4; ++mi)
        arow_off[mi] = (uint32_t)((wm * 64 + mi * 16 + (lane & 15)) * 128);
    #pragma unroll
    for (int nj = 0; nj < 2; ++nj)
        brow_off[nj] = (uint32_t)((wn * 32 + nj * 16 + ((lane >> 4) << 3) + (lane & 7)) * 128);
    const uint32_t swz = (uint32_t)(lane & 7);

    float acc[4][4][4];
    #pragma unroll
    for (int mi = 0; mi < 4; ++mi)
        #pragma unroll
        for (int nt = 0; nt < 4; ++nt)
            #pragma unroll
            for (int k = 0; k < 4; ++k) acc[mi][nt][k] = 0.f;

    // -------- staging: one K-chunk (tap t, ic block icb64) into buffer st --------
    auto issue = [&](int st, int it) {
        const int t = it >> 3, icb = (it & 7) << 6;
        const int dh = t / 3, dw = t - dh * 3;
        const uint32_t s0 = sb + (uint32_t)st * 65536u;
        #pragma unroll
        for (int k2 = 0; k2 < 4; ++k2) {
            int q = tid + (k2 << 8);                 // 0..1023
            int row = q >> 3, cc = q & 7;
            uint32_t doff = (uint32_t)(row * 128 + (((uint32_t)cc ^ (uint32_t)(row & 7)) << 4));
            size_t wsrc = ((size_t)t * COUT + ocb + row) * CIN + icb + (cc << 3);
            cp16(s0 + doff,          g_wph + wsrc);
            cp16(s0 + 16384 + doff,  g_wpl + wsrc);
            int pr = row >> 6, pc = row & 63;
            size_t xsrc = ((size_t)(rp * 2 + pr + dh) * 66 + (pc + dw)) * 512 + icb + (cc << 3);
            cp16(s0 + 32768 + doff,  xbh + xsrc);
            cp16(s0 + 49152 + doff,  xbl + xsrc);
        }
        cp_commit();
    };

    issue(0, 0);
    for (int it = 0; it < 72; ++it) {
        if (it < 71) { issue((it + 1) & 1, it + 1); cp_wait<1>(); }
        else         { cp_wait<0>(); }
        __syncthreads();

        const uint32_t s0 = sb + (uint32_t)(it & 1) * 65536u;
        #pragma unroll
        for (int ks = 0; ks < 4; ++ks) {
            const uint32_t ca = (((uint32_t)(2 * ks) + (uint32_t)(lane >> 4)) ^ swz) << 4;
            const uint32_t cb = (((uint32_t)(2 * ks) + (uint32_t)((lane >> 3) & 1)) ^ swz) << 4;
            uint32_t Ah[4][4], Al[4][4], Bh[2][4], Bl[2][4];
            #pragma unroll
            for (int mi = 0; mi < 4; ++mi) {
                LDSM4(Ah[mi], s0 + arow_off[mi] + ca);
                LDSM4(Al[mi], s0 + 16384 + arow_off[mi] + ca);
            }
            #pragma unroll
            for (int nj = 0; nj < 2; ++nj) {
                LDSM4(Bh[nj], s0 + 32768 + brow_off[nj] + cb);
                LDSM4(Bl[nj], s0 + 49152 + brow_off[nj] + cb);
            }
            #pragma unroll
            for (int mi = 0; mi < 4; ++mi)
                #pragma unroll
                for (int nt = 0; nt < 4; ++nt) {
                    const int nj = nt >> 1, hp = (nt & 1) << 1;
                    MMA(acc[mi][nt], Ah[mi], Bh[nj][hp], Bh[nj][hp + 1]);
                    MMA(acc[mi][nt], Al[mi], Bh[nj][hp], Bh[nj][hp + 1]);
                    MMA(acc[mi][nt], Ah[mi], Bl[nj][hp], Bl[nj][hp + 1]);
                }
        }
        __syncthreads();
    }

    // -------- epilogue: demod scale + store --------
    const int r0c = lane >> 2, cp2 = (lane & 3) << 1;
    #pragma unroll
    for (int mi = 0; mi < 4; ++mi) {
        const int oc0 = ocb + wm * 64 + mi * 16 + r0c, oc1 = oc0 + 8;
        const float d0 = g_demod[b * COUT + oc0];
        const float d1 = g_demod[b * COUT + oc1];
        float* p0 = out + ((size_t)b * COUT + oc0) * 4096 + rp * 128;
        float* p1 = out + ((size_t)b * COUT + oc1) * 4096 + rp * 128;
        #pragma unroll
        for (int nt = 0; nt < 4; ++nt) {
            const int nc = wn * 32 + nt * 8 + cp2;
            float2 v0 = make_float2(acc[mi][nt][0] * d0, acc[mi][nt][1] * d0);
            float2 v1 = make_float2(acc[mi][nt][2] * d1, acc[mi][nt][3] * d1);
            *(float2*)(p0 + nc) = v0;
            *(float2*)(p1 + nc) = v1;
        }
    }
}

// ---------------- launch ----------------
extern "C" void kernel_launch(void* const* d_in, const int* in_sizes, int n_in,
                              void* d_out, int out_size) {
    const float* input  = (const float*)d_in[0];  // (16,512,64,64)
    const float* style  = (const float*)d_in[1];  // (16,512)
    const float* weight = (const float*)d_in[2];  // (512,512,3,3)
    const float* mod_w  = (const float*)d_in[3];  // (512,512)
    const float* mod_b  = (const float*)d_in[4];  // (512,)
    float* out = (float*)d_out;                   // (16,512,64,64)
    (void)in_sizes; (void)n_in; (void)out_size;

    k_mod   <<<1024, 256>>>(style, mod_w, mod_b);
    k_wsq   <<<1024, 256>>>(weight);
    k_demod <<<1024, 256>>>();
    k_wprep <<<1024, 256>>>(weight);
    k_border<<<(BB * 66 * 66 + 255) / 256, 256>>>();
    k_xprep <<<dim3(64, 16), 256>>>(input);

    cudaFuncSetAttribute(k_conv_mma, cudaFuncAttributeMaxDynamicSharedMemorySize, 131072);
    k_conv_mma<<<dim3(32, 4, 16), 256, 131072>>>(out);
}

// round 9
// speedup vs baseline: 6.1412x; 1.4238x over previous
#include <cuda_runtime.h>
#include <cuda_fp16.h>
#include <cstdint>

#define BB   16
#define CIN  512
#define COUT 512
#define HH   64
#define WW   64
#define SS   512

// ---------------- scratch (__device__ globals: allocation-free) ----------------
__device__ float g_smod[BB * CIN];      // s[b][i]
__device__ float g_demod[BB * COUT];    // demod[b][o]
__device__ float g_wsq[COUT * CIN];     // per-(o,i) 3x3 weight energy

// split weights, [t][oc][ic], fp16 hi/lo
__device__ __align__(16) unsigned short g_wph[9 * COUT * CIN];
__device__ __align__(16) unsigned short g_wpl[9 * COUT * CIN];
// padded modulated input, channel-last [b][66][66][ic], fp16
__device__ __align__(16) unsigned short g_xp[35684352];

// ---------------- baseline-ISA helpers (sm_80-era: safe at .target sm_103) ----
__device__ __forceinline__ void cp16(uint32_t dst, const void* src) {
    asm volatile("cp.async.cg.shared.global [%0], [%1], 16;" :: "r"(dst), "l"(src) : "memory");
}
__device__ __forceinline__ void cp_commit() { asm volatile("cp.async.commit_group;" ::: "memory"); }
template <int N> __device__ __forceinline__ void cp_wait() {
    asm volatile("cp.async.wait_group %0;" :: "n"(N) : "memory");
}
#define LDSM4(r, addr) \
    asm volatile("ldmatrix.sync.aligned.m8n8.x4.shared.b16 {%0,%1,%2,%3}, [%4];" \
                 : "=r"((r)[0]), "=r"((r)[1]), "=r"((r)[2]), "=r"((r)[3]) : "r"(addr))
#define MMA(c, a, b0v, b1v) \
    asm volatile("mma.sync.aligned.m16n8k16.row.col.f32.f16.f16.f32 " \
                 "{%0,%1,%2,%3}, {%4,%5,%6,%7}, {%8,%9}, {%0,%1,%2,%3};" \
                 : "+f"((c)[0]), "+f"((c)[1]), "+f"((c)[2]), "+f"((c)[3]) \
                 : "r"((a)[0]), "r"((a)[1]), "r"((a)[2]), "r"((a)[3]), "r"(b0v), "r"(b1v))

// ---------------- kernel 1: s = style @ mod_w^T + mod_b ----------------
__global__ void k_mod(const float* __restrict__ style, const float* __restrict__ mod_w,
                      const float* __restrict__ mod_b) {
    int wid  = (blockIdx.x * blockDim.x + threadIdx.x) >> 5;
    int lane = threadIdx.x & 31;
    if (wid >= BB * CIN) return;
    int b = wid >> 9, i = wid & 511;
    const float* st = style + b * SS;
    const float* mw = mod_w + (size_t)i * SS;
    float sum = 0.f;
    for (int l = lane; l < SS; l += 32) sum += st[l] * mw[l];
    #pragma unroll
    for (int o = 16; o > 0; o >>= 1) sum += __shfl_xor_sync(0xffffffffu, sum, o);
    if (lane == 0) g_smod[wid] = sum + mod_b[i];
}

// ---------------- kernel 2: wsq ----------------
__global__ void k_wsq(const float* __restrict__ weight) {
    int idx = blockIdx.x * blockDim.x + threadIdx.x;
    if (idx >= COUT * CIN) return;
    const float* w = weight + (size_t)idx * 9;
    float s = 0.f;
    #pragma unroll
    for (int t = 0; t < 9; ++t) s += w[t] * w[t];
    g_wsq[idx] = s;
}

// ---------------- kernel 3: demod ----------------
__global__ void k_demod() {
    int wid  = (blockIdx.x * blockDim.x + threadIdx.x) >> 5;
    int lane = threadIdx.x & 31;
    if (wid >= BB * COUT) return;
    int b = wid >> 9, o = wid & 511;
    const float* wsq = g_wsq + (size_t)o * CIN;
    const float* sm  = g_smod + b * CIN;
    float sum = 0.f;
    for (int i = lane; i < CIN; i += 32) { float s = sm[i]; sum += wsq[i] * s * s; }
    #pragma unroll
    for (int off = 16; off > 0; off >>= 1) sum += __shfl_xor_sync(0xffffffffu, sum, off);
    const float scale2 = 2.1701389e-4f;   // 1/(Cin*K*K)
    if (lane == 0) g_demod[wid] = rsqrtf(scale2 * sum + 1e-8f);
}

// ---------------- kernel 4: split weights -> [t][oc][ic] fp16 hi/lo ----------------
__global__ void k_wprep(const float* __restrict__ weight) {
    int idx = blockIdx.x * 256 + threadIdx.x;
    if (idx >= COUT * CIN) return;
    int oc = idx >> 9, ic = idx & 511;
    const float* w = weight + (size_t)idx * 9;
    #pragma unroll
    for (int t = 0; t < 9; ++t) {
        float x = w[t];
        __half h = __float2half_rn(x);
        float hf = __half2float(h);
        __half l = __float2half_rn(x - hf);
        size_t o = ((size_t)t * COUT + oc) * CIN + ic;
        g_wph[o] = __half_as_ushort(h);
        g_wpl[o] = __half_as_ushort(l);
    }
}

// ---------------- kernel 5: zero pad border of xp ----------------
__global__ void k_border() {
    int idx = blockIdx.x * 256 + threadIdx.x;   // b*4356 + rr*66 + cc
    if (idx >= BB * 66 * 66) return;
    int cell = idx % 4356;
    int rr = cell / 66, cc = cell % 66;
    if (rr == 0 || rr == 65 || cc == 0 || cc == 65) {
        size_t o = (size_t)idx * 512;
        uint4 z = make_uint4(0, 0, 0, 0);
        #pragma unroll
        for (int k = 0; k < 64; ++k)
            *(uint4*)(g_xp + o + k * 8) = z;
    }
}

// ---------------- kernel 6: modulate + round + transpose input -> xp (fp16) ----------------
__global__ void __launch_bounds__(256)
k_xprep(const float* __restrict__ input) {
    __shared__ __align__(16) unsigned short sh[64 * 128];
    const int r = blockIdx.x, b = blockIdx.y, tid = threadIdx.x;
    const float scale = 0.014731391f;   // 1/sqrt(4608)
    for (int icb = 0; icb < CIN; icb += 128) {
        #pragma unroll
        for (int k = 0; k < 8; ++k) {
            int idx = tid + (k << 8);
            int icl = idx >> 4, c4 = idx & 15;
            int ic  = icb + icl;
            float s = scale * g_smod[b * CIN + ic];
            float4 v = *(const float4*)(input + ((size_t)(b * CIN + ic) * HH + r) * WW + (c4 << 2));
            float xs[4] = {v.x * s, v.y * s, v.z * s, v.w * s};
            #pragma unroll
            for (int j = 0; j < 4; ++j) {
                int c = (c4 << 2) + j;
                sh[c * 128 + icl] = __half_as_ushort(__float2half_rn(xs[j]));
            }
        }
        __syncthreads();
        #pragma unroll
        for (int k = 0; k < 2; ++k) {
            int q = tid + (k << 8);
            int c = q >> 3, kk = q & 7;
            size_t dst = (((size_t)b * 66 + r + 1) * 66 + c + 1) * 512 + icb + (kk << 4);
            *(uint4*)(g_xp + dst)     = *(const uint4*)(sh + c * 128 + (kk << 4));
            *(uint4*)(g_xp + dst + 8) = *(const uint4*)(sh + c * 128 + (kk << 4) + 8);
        }
        __syncthreads();
    }
}

// ---------------- kernel 7: warp-MMA implicit-GEMM conv (fp16, 2-term split) ---------
// CTA: M=128 oc x N=128 px (2 rows). 8 warps (2x4), warp tile 64x32.
// K: 9 taps x 8 ic-chunks of 64; per k16 step 2 MMAs (wh*xh + wl*xh).
// 3-stage cp.async ring (48KB/stage), SW128-style XOR swizzle, conflict-free ldmatrix.
__global__ void __launch_bounds__(256, 1)
k_conv_mma(float* __restrict__ out) {
    extern __shared__ char dsm[];
    const int tid = threadIdx.x, lane = tid & 31, wid = tid >> 5;
    const int wm = wid >> 2, wn = wid & 3;
    const int b = blockIdx.z, ocb = blockIdx.y << 7, rp = blockIdx.x;  // rp: row-pair 0..31

    const uint32_t sb = (uint32_t)__cvta_generic_to_shared(dsm);
    const unsigned short* __restrict__ xb = g_xp + (size_t)b * 66 * 66 * 512;

    // ldmatrix row offsets (fixed per thread)
    uint32_t arow_off[4], brow_off[2];
    #pragma unroll
    for (int mi = 0; mi < 4; ++mi)
        arow_off[mi] = (uint32_t)((wm * 64 + mi * 16 + (lane & 15)) * 128);
    #pragma unroll
    for (int nj = 0; nj < 2; ++nj)
        brow_off[nj] = (uint32_t)((wn * 32 + nj * 16 + ((lane >> 4) << 3) + (lane & 7)) * 128);
    const uint32_t swz = (uint32_t)(lane & 7);

    float acc[4][4][4];
    #pragma unroll
    for (int mi = 0; mi < 4; ++mi)
        #pragma unroll
        for (int nt = 0; nt < 4; ++nt)
            #pragma unroll
            for (int k = 0; k < 4; ++k) acc[mi][nt][k] = 0.f;

    // stage layout: {Wh:0, Wl:16K, Xh:32K}, 48KB per stage, 3 stages
    auto issue = [&](int it) {
        const int st = it % 3;
        const int t = it >> 3, icb = (it & 7) << 6;
        const int dh = t / 3, dw = t - dh * 3;
        const uint32_t s0 = sb + (uint32_t)st * 49152u;
        #pragma unroll
        for (int k2 = 0; k2 < 4; ++k2) {
            int q = tid + (k2 << 8);                 // 0..1023
            int row = q >> 3, cc = q & 7;
            uint32_t doff = (uint32_t)(row * 128 + (((uint32_t)cc ^ (uint32_t)(row & 7)) << 4));
            size_t wsrc = ((size_t)t * COUT + ocb + row) * CIN + icb + (cc << 3);
            cp16(s0 + doff,          g_wph + wsrc);
            cp16(s0 + 16384 + doff,  g_wpl + wsrc);
            int pr = row >> 6, pc = row & 63;
            size_t xsrc = ((size_t)(rp * 2 + pr + dh) * 66 + (pc + dw)) * 512 + icb + (cc << 3);
            cp16(s0 + 32768 + doff,  xb + xsrc);
        }
        cp_commit();
    };

    issue(0);
    issue(1);
    for (int it = 0; it < 72; ++it) {
        if (it < 70)        { issue(it + 2); cp_wait<2>(); }
        else if (it == 70)  { cp_wait<1>(); }
        else                { cp_wait<0>(); }
        __syncthreads();

        const uint32_t s0 = sb + (uint32_t)(it % 3) * 49152u;
        #pragma unroll
        for (int ks = 0; ks < 4; ++ks) {
            const uint32_t ca = (((uint32_t)(2 * ks) + (uint32_t)(lane >> 4)) ^ swz) << 4;
            const uint32_t cb = (((uint32_t)(2 * ks) + (uint32_t)((lane >> 3) & 1)) ^ swz) << 4;
            uint32_t Ah[4][4], Al[4][4], Bh[2][4];
            #pragma unroll
            for (int mi = 0; mi < 4; ++mi) {
                LDSM4(Ah[mi], s0 + arow_off[mi] + ca);
                LDSM4(Al[mi], s0 + 16384 + arow_off[mi] + ca);
            }
            #pragma unroll
            for (int nj = 0; nj < 2; ++nj)
                LDSM4(Bh[nj], s0 + 32768 + brow_off[nj] + cb);
            #pragma unroll
            for (int mi = 0; mi < 4; ++mi)
                #pragma unroll
                for (int nt = 0; nt < 4; ++nt) {
                    const int nj = nt >> 1, hp = (nt & 1) << 1;
                    MMA(acc[mi][nt], Ah[mi], Bh[nj][hp], Bh[nj][hp + 1]);
                    MMA(acc[mi][nt], Al[mi], Bh[nj][hp], Bh[nj][hp + 1]);
                }
        }
        __syncthreads();
    }

    // -------- epilogue: demod scale + store --------
    const int r0c = lane >> 2, cp2 = (lane & 3) << 1;
    #pragma unroll
    for (int mi = 0; mi < 4; ++mi) {
        const int oc0 = ocb + wm * 64 + mi * 16 + r0c, oc1 = oc0 + 8;
        const float d0 = g_demod[b * COUT + oc0];
        const float d1 = g_demod[b * COUT + oc1];
        float* p0 = out + ((size_t)b * COUT + oc0) * 4096 + rp * 128;
        float* p1 = out + ((size_t)b * COUT + oc1) * 4096 + rp * 128;
        #pragma unroll
        for (int nt = 0; nt < 4; ++nt) {
            const int nc = wn * 32 + nt * 8 + cp2;
            float2 v0 = make_float2(acc[mi][nt][0] * d0, acc[mi][nt][1] * d0);
            float2 v1 = make_float2(acc[mi][nt][2] * d1, acc[mi][nt][3] * d1);
            *(float2*)(p0 + nc) = v0;
            *(float2*)(p1 + nc) = v1;
        }
    }
}

// ---------------- launch ----------------
extern "C" void kernel_launch(void* const* d_in, const int* in_sizes, int n_in,
                              void* d_out, int out_size) {
    const float* input  = (const float*)d_in[0];  // (16,512,64,64)
    const float* style  = (const float*)d_in[1];  // (16,512)
    const float* weight = (const float*)d_in[2];  // (512,512,3,3)
    const float* mod_w  = (const float*)d_in[3];  // (512,512)
    const float* mod_b  = (const float*)d_in[4];  // (512,)
    float* out = (float*)d_out;                   // (16,512,64,64)
    (void)in_sizes; (void)n_in; (void)out_size;

    k_mod   <<<1024, 256>>>(style, mod_w, mod_b);
    k_wsq   <<<1024, 256>>>(weight);
    k_demod <<<1024, 256>>>();
    k_wprep <<<1024, 256>>>(weight);
    k_border<<<(BB * 66 * 66 + 255) / 256, 256>>>();
    k_xprep <<<dim3(64, 16), 256>>>(input);

    cudaFuncSetAttribute(k_conv_mma, cudaFuncAttributeMaxDynamicSharedMemorySize, 147456);
    k_conv_mma<<<dim3(32, 4, 16), 256, 147456>>>(out);
}

// round 11
// speedup vs baseline: 7.5271x; 1.2257x over previous
#include <cuda_runtime.h>
#include <cuda_fp16.h>
#include <cstdint>

#define BB   16
#define CIN  512
#define COUT 512
#define HH   64
#define WW   64
#define SS   512

// ---------------- scratch (__device__ globals: allocation-free) ----------------
__device__ float g_smod[BB * CIN];      // s[b][i]
__device__ float g_demod[BB * COUT];    // demod[b][o]
__device__ float g_wsq[COUT * CIN];     // per-(o,i) 3x3 weight energy

// fp16 weights, [t][oc][ic]
__device__ __align__(16) unsigned short g_wp[9 * COUT * CIN];
// padded modulated input, channel-last [b][66][66][ic], fp16
__device__ __align__(16) unsigned short g_xp[35684352];

// ---------------- baseline-ISA helpers (sm_80-era: safe at .target sm_103) ----
__device__ __forceinline__ void cp16(uint32_t dst, const void* src) {
    asm volatile("cp.async.cg.shared.global [%0], [%1], 16;" :: "r"(dst), "l"(src) : "memory");
}
__device__ __forceinline__ void cp_commit() { asm volatile("cp.async.commit_group;" ::: "memory"); }
template <int N> __device__ __forceinline__ void cp_wait() {
    asm volatile("cp.async.wait_group %0;" :: "n"(N) : "memory");
}
#define LDSM4(r, addr) \
    asm volatile("ldmatrix.sync.aligned.m8n8.x4.shared.b16 {%0,%1,%2,%3}, [%4];" \
                 : "=r"((r)[0]), "=r"((r)[1]), "=r"((r)[2]), "=r"((r)[3]) : "r"(addr))
#define MMA(c, a, b0v, b1v) \
    asm volatile("mma.sync.aligned.m16n8k16.row.col.f32.f16.f16.f32 " \
                 "{%0,%1,%2,%3}, {%4,%5,%6,%7}, {%8,%9}, {%0,%1,%2,%3};" \
                 : "+f"((c)[0]), "+f"((c)[1]), "+f"((c)[2]), "+f"((c)[3]) \
                 : "r"((a)[0]), "r"((a)[1]), "r"((a)[2]), "r"((a)[3]), "r"(b0v), "r"(b1v))

// ---------------- kernel 1: s = style @ mod_w^T + mod_b ----------------
__global__ void k_mod(const float* __restrict__ style, const float* __restrict__ mod_w,
                      const float* __restrict__ mod_b) {
    int wid  = (blockIdx.x * blockDim.x + threadIdx.x) >> 5;
    int lane = threadIdx.x & 31;
    if (wid >= BB * CIN) return;
    int b = wid >> 9, i = wid & 511;
    const float* st = style + b * SS;
    const float* mw = mod_w + (size_t)i * SS;
    float sum = 0.f;
    for (int l = lane; l < SS; l += 32) sum += st[l] * mw[l];
    #pragma unroll
    for (int o = 16; o > 0; o >>= 1) sum += __shfl_xor_sync(0xffffffffu, sum, o);
    if (lane == 0) g_smod[wid] = sum + mod_b[i];
}

// ---------------- kernel 2: wsq ----------------
__global__ void k_wsq(const float* __restrict__ weight) {
    int idx = blockIdx.x * blockDim.x + threadIdx.x;
    if (idx >= COUT * CIN) return;
    const float* w = weight + (size_t)idx * 9;
    float s = 0.f;
    #pragma unroll
    for (int t = 0; t < 9; ++t) s += w[t] * w[t];
    g_wsq[idx] = s;
}

// ---------------- kernel 3: demod ----------------
__global__ void k_demod() {
    int wid  = (blockIdx.x * blockDim.x + threadIdx.x) >> 5;
    int lane = threadIdx.x & 31;
    if (wid >= BB * COUT) return;
    int b = wid >> 9, o = wid & 511;
    const float* wsq = g_wsq + (size_t)o * CIN;
    const float* sm  = g_smod + b * CIN;
    float sum = 0.f;
    for (int i = lane; i < CIN; i += 32) { float s = sm[i]; sum += wsq[i] * s * s; }
    #pragma unroll
    for (int off = 16; off > 0; off >>= 1) sum += __shfl_xor_sync(0xffffffffu, sum, off);
    const float scale2 = 2.1701389e-4f;   // 1/(Cin*K*K)
    if (lane == 0) g_demod[wid] = rsqrtf(scale2 * sum + 1e-8f);
}

// ---------------- kernel 4: weights -> [t][oc][ic] fp16 ----------------
__global__ void k_wprep(const float* __restrict__ weight) {
    int idx = blockIdx.x * 256 + threadIdx.x;
    if (idx >= COUT * CIN) return;
    int oc = idx >> 9, ic = idx & 511;
    const float* w = weight + (size_t)idx * 9;
    #pragma unroll
    for (int t = 0; t < 9; ++t) {
        size_t o = ((size_t)t * COUT + oc) * CIN + ic;
        g_wp[o] = __half_as_ushort(__float2half_rn(w[t]));
    }
}

// ---------------- kernel 5: zero pad border of xp ----------------
__global__ void k_border() {
    int idx = blockIdx.x * 256 + threadIdx.x;   // b*4356 + rr*66 + cc
    if (idx >= BB * 66 * 66) return;
    int cell = idx % 4356;
    int rr = cell / 66, cc = cell % 66;
    if (rr == 0 || rr == 65 || cc == 0 || cc == 65) {
        size_t o = (size_t)idx * 512;
        uint4 z = make_uint4(0, 0, 0, 0);
        #pragma unroll
        for (int k = 0; k < 64; ++k)
            *(uint4*)(g_xp + o + k * 8) = z;
    }
}

// ---------------- kernel 6: modulate + round + transpose input -> xp (fp16) ----------------
__global__ void __launch_bounds__(256)
k_xprep(const float* __restrict__ input) {
    __shared__ __align__(16) unsigned short sh[64 * 128];
    const int r = blockIdx.x, b = blockIdx.y, tid = threadIdx.x;
    const float scale = 0.014731391f;   // 1/sqrt(4608)
    for (int icb = 0; icb < CIN; icb += 128) {
        #pragma unroll
        for (int k = 0; k < 8; ++k) {
            int idx = tid + (k << 8);
            int icl = idx >> 4, c4 = idx & 15;
            int ic  = icb + icl;
            float s = scale * g_smod[b * CIN + ic];
            float4 v = *(const float4*)(input + ((size_t)(b * CIN + ic) * HH + r) * WW + (c4 << 2));
            float xs[4] = {v.x * s, v.y * s, v.z * s, v.w * s};
            #pragma unroll
            for (int j = 0; j < 4; ++j) {
                int c = (c4 << 2) + j;
                sh[c * 128 + icl] = __half_as_ushort(__float2half_rn(xs[j]));
            }
        }
        __syncthreads();
        #pragma unroll
        for (int k = 0; k < 2; ++k) {
            int q = tid + (k << 8);
            int c = q >> 3, kk = q & 7;
            size_t dst = (((size_t)b * 66 + r + 1) * 66 + c + 1) * 512 + icb + (kk << 4);
            *(uint4*)(g_xp + dst)     = *(const uint4*)(sh + c * 128 + (kk << 4));
            *(uint4*)(g_xp + dst + 8) = *(const uint4*)(sh + c * 128 + (kk << 4) + 8);
        }
        __syncthreads();
    }
}

// ---------------- kernel 7: warp-MMA implicit-GEMM conv (fp16, single-term) ---------
// CTA: M=128 oc x N=128 px (2 rows). 8 warps (2x4), warp tile 64x32.
// K: 9 taps x 8 ic-chunks of 64; 1 MMA per k16 step.
// 3-stage cp.async ring (32KB/stage = 96KB), 2 CTAs/SM target.
__global__ void __launch_bounds__(256, 2)
k_conv_mma(float* __restrict__ out) {
    extern __shared__ char dsm[];
    const int tid = threadIdx.x, lane = tid & 31, wid = tid >> 5;
    const int wm = wid >> 2, wn = wid & 3;
    const int b = blockIdx.z, ocb = blockIdx.y << 7, rp = blockIdx.x;  // rp: row-pair 0..31

    const uint32_t sb = (uint32_t)__cvta_generic_to_shared(dsm);
    const unsigned short* __restrict__ xb = g_xp + (size_t)b * 66 * 66 * 512;

    // ldmatrix row offsets (fixed per thread)
    uint32_t arow_off[4], brow_off[2];
    #pragma unroll
    for (int mi = 0; mi < 4; ++mi)
        arow_off[mi] = (uint32_t)((wm * 64 + mi * 16 + (lane & 15)) * 128);
    #pragma unroll
    for (int nj = 0; nj < 2; ++nj)
        brow_off[nj] = (uint32_t)((wn * 32 + nj * 16 + ((lane >> 4) << 3) + (lane & 7)) * 128);
    const uint32_t swz = (uint32_t)(lane & 7);

    float acc[4][4][4];
    #pragma unroll
    for (int mi = 0; mi < 4; ++mi)
        #pragma unroll
        for (int nt = 0; nt < 4; ++nt)
            #pragma unroll
            for (int k = 0; k < 4; ++k) acc[mi][nt][k] = 0.f;

    // stage layout: {W:0, X:16K}, 32KB per stage, 3 stages
    auto issue = [&](int it) {
        const int st = it % 3;
        const int t = it >> 3, icb = (it & 7) << 6;
        const int dh = t / 3, dw = t - dh * 3;
        const uint32_t s0 = sb + (uint32_t)st * 32768u;
        #pragma unroll
        for (int k2 = 0; k2 < 4; ++k2) {
            int q = tid + (k2 << 8);                 // 0..1023
            int row = q >> 3, cc = q & 7;
            uint32_t doff = (uint32_t)(row * 128 + (((uint32_t)cc ^ (uint32_t)(row & 7)) << 4));
            size_t wsrc = ((size_t)t * COUT + ocb + row) * CIN + icb + (cc << 3);
            cp16(s0 + doff, g_wp + wsrc);
            int pr = row >> 6, pc = row & 63;
            size_t xsrc = ((size_t)(rp * 2 + pr + dh) * 66 + (pc + dw)) * 512 + icb + (cc << 3);
            cp16(s0 + 16384 + doff, xb + xsrc);
        }
        cp_commit();
    };

    issue(0);
    issue(1);
    for (int it = 0; it < 72; ++it) {
        if (it < 70)        { issue(it + 2); cp_wait<2>(); }
        else if (it == 70)  { cp_wait<1>(); }
        else                { cp_wait<0>(); }
        __syncthreads();

        const uint32_t s0 = sb + (uint32_t)(it % 3) * 32768u;
        #pragma unroll
        for (int ks = 0; ks < 4; ++ks) {
            const uint32_t ca = (((uint32_t)(2 * ks) + (uint32_t)(lane >> 4)) ^ swz) << 4;
            const uint32_t cb = (((uint32_t)(2 * ks) + (uint32_t)((lane >> 3) & 1)) ^ swz) << 4;
            uint32_t Ah[4][4], Bh[2][4];
            #pragma unroll
            for (int mi = 0; mi < 4; ++mi)
                LDSM4(Ah[mi], s0 + arow_off[mi] + ca);
            #pragma unroll
            for (int nj = 0; nj < 2; ++nj)
                LDSM4(Bh[nj], s0 + 16384 + brow_off[nj] + cb);
            #pragma unroll
            for (int mi = 0; mi < 4; ++mi)
                #pragma unroll
                for (int nt = 0; nt < 4; ++nt) {
                    const int nj = nt >> 1, hp = (nt & 1) << 1;
                    MMA(acc[mi][nt], Ah[mi], Bh[nj][hp], Bh[nj][hp + 1]);
                }
        }
        __syncthreads();
    }

    // -------- epilogue: demod scale + store --------
    const int r0c = lane >> 2, cp2 = (lane & 3) << 1;
    #pragma unroll
    for (int mi = 0; mi < 4; ++mi) {
        const int oc0 = ocb + wm * 64 + mi * 16 + r0c, oc1 = oc0 + 8;
        const float d0 = g_demod[b * COUT + oc0];
        const float d1 = g_demod[b * COUT + oc1];
        float* p0 = out + ((size_t)b * COUT + oc0) * 4096 + rp * 128;
        float* p1 = out + ((size_t)b * COUT + oc1) * 4096 + rp * 128;
        #pragma unroll
        for (int nt = 0; nt < 4; ++nt) {
            const int nc = wn * 32 + nt * 8 + cp2;
            float2 v0 = make_float2(acc[mi][nt][0] * d0, acc[mi][nt][1] * d0);
            float2 v1 = make_float2(acc[mi][nt][2] * d1, acc[mi][nt][3] * d1);
            *(float2*)(p0 + nc) = v0;
            *(float2*)(p1 + nc) = v1;
        }
    }
}

// ---------------- launch ----------------
extern "C" void kernel_launch(void* const* d_in, const int* in_sizes, int n_in,
                              void* d_out, int out_size) {
    const float* input  = (const float*)d_in[0];  // (16,512,64,64)
    const float* style  = (const float*)d_in[1];  // (16,512)
    const float* weight = (const float*)d_in[2];  // (512,512,3,3)
    const float* mod_w  = (const float*)d_in[3];  // (512,512)
    const float* mod_b  = (const float*)d_in[4];  // (512,)
    float* out = (float*)d_out;                   // (16,512,64,64)
    (void)in_sizes; (void)n_in; (void)out_size;

    k_mod   <<<1024, 256>>>(style, mod_w, mod_b);
    k_wsq   <<<1024, 256>>>(weight);
    k_demod <<<1024, 256>>>();
    k_wprep <<<1024, 256>>>(weight);
    k_border<<<(BB * 66 * 66 + 255) / 256, 256>>>();
    k_xprep <<<dim3(64, 16), 256>>>(input);

    cudaFuncSetAttribute(k_conv_mma, cudaFuncAttributeMaxDynamicSharedMemorySize, 98304);
    k_conv_mma<<<dim3(32, 4, 16), 256, 98304>>>(out);
}

// round 12
// speedup vs baseline: 11.7402x; 1.5597x over previous
#include <cuda_runtime.h>
#include <cuda_fp16.h>
#include <cstdint>

#define BB   16
#define CIN  512
#define COUT 512
#define HH   64
#define WW   64
#define SS   512

// ---------------- scratch (__device__ globals: allocation-free) ----------------
__device__ float g_smod[BB * CIN];      // s[b][i]
__device__ float g_demod[BB * COUT];    // demod[b][o]
__device__ float g_wsq[COUT * CIN];     // per-(o,i) 3x3 weight energy

// fp16 weights, [t][oc][ic]
__device__ __align__(16) unsigned short g_wp[9 * COUT * CIN];
// padded modulated input, channel-last [b][66][66][ic], fp16
__device__ __align__(16) unsigned short g_xp[35684352];

// ---------------- baseline-ISA helpers (sm_80-era: safe at .target sm_103) ----
__device__ __forceinline__ void cp16(uint32_t dst, const void* src) {
    asm volatile("cp.async.cg.shared.global [%0], [%1], 16;" :: "r"(dst), "l"(src) : "memory");
}
__device__ __forceinline__ void cp_commit() { asm volatile("cp.async.commit_group;" ::: "memory"); }
template <int N> __device__ __forceinline__ void cp_wait() {
    asm volatile("cp.async.wait_group %0;" :: "n"(N) : "memory");
}
#define LDSM4(r, addr) \
    asm volatile("ldmatrix.sync.aligned.m8n8.x4.shared.b16 {%0,%1,%2,%3}, [%4];" \
                 : "=r"((r)[0]), "=r"((r)[1]), "=r"((r)[2]), "=r"((r)[3]) : "r"(addr))
#define MMA(c, a, b0v, b1v) \
    asm volatile("mma.sync.aligned.m16n8k16.row.col.f32.f16.f16.f32 " \
                 "{%0,%1,%2,%3}, {%4,%5,%6,%7}, {%8,%9}, {%0,%1,%2,%3};" \
                 : "+f"((c)[0]), "+f"((c)[1]), "+f"((c)[2]), "+f"((c)[3]) \
                 : "r"((a)[0]), "r"((a)[1]), "r"((a)[2]), "r"((a)[3]), "r"(b0v), "r"(b1v))

// ---------------- kernel 1: s = style @ mod_w^T + mod_b ----------------
__global__ void k_mod(const float* __restrict__ style, const float* __restrict__ mod_w,
                      const float* __restrict__ mod_b) {
    int wid  = (blockIdx.x * blockDim.x + threadIdx.x) >> 5;
    int lane = threadIdx.x & 31;
    if (wid >= BB * CIN) return;
    int b = wid >> 9, i = wid & 511;
    const float* st = style + b * SS;
    const float* mw = mod_w + (size_t)i * SS;
    float sum = 0.f;
    for (int l = lane; l < SS; l += 32) sum += st[l] * mw[l];
    #pragma unroll
    for (int o = 16; o > 0; o >>= 1) sum += __shfl_xor_sync(0xffffffffu, sum, o);
    if (lane == 0) g_smod[wid] = sum + mod_b[i];
}

// ---------------- kernel 2: wsq ----------------
__global__ void k_wsq(const float* __restrict__ weight) {
    int idx = blockIdx.x * blockDim.x + threadIdx.x;
    if (idx >= COUT * CIN) return;
    const float* w = weight + (size_t)idx * 9;
    float s = 0.f;
    #pragma unroll
    for (int t = 0; t < 9; ++t) s += w[t] * w[t];
    g_wsq[idx] = s;
}

// ---------------- kernel 3: demod ----------------
__global__ void k_demod() {
    int wid  = (blockIdx.x * blockDim.x + threadIdx.x) >> 5;
    int lane = threadIdx.x & 31;
    if (wid >= BB * COUT) return;
    int b = wid >> 9, o = wid & 511;
    const float* wsq = g_wsq + (size_t)o * CIN;
    const float* sm  = g_smod + b * CIN;
    float sum = 0.f;
    for (int i = lane; i < CIN; i += 32) { float s = sm[i]; sum += wsq[i] * s * s; }
    #pragma unroll
    for (int off = 16; off > 0; off >>= 1) sum += __shfl_xor_sync(0xffffffffu, sum, off);
    const float scale2 = 2.1701389e-4f;   // 1/(Cin*K*K)
    if (lane == 0) g_demod[wid] = rsqrtf(scale2 * sum + 1e-8f);
}

// ---------------- kernel 4: weights -> [t][oc][ic] fp16 ----------------
__global__ void k_wprep(const float* __restrict__ weight) {
    int idx = blockIdx.x * 256 + threadIdx.x;
    if (idx >= COUT * CIN) return;
    int oc = idx >> 9, ic = idx & 511;
    const float* w = weight + (size_t)idx * 9;
    #pragma unroll
    for (int t = 0; t < 9; ++t) {
        size_t o = ((size_t)t * COUT + oc) * CIN + ic;
        g_wp[o] = __half_as_ushort(__float2half_rn(w[t]));
    }
}

// ---------------- kernel 5: zero pad border of xp ----------------
__global__ void k_border() {
    int idx = blockIdx.x * 256 + threadIdx.x;   // b*4356 + rr*66 + cc
    if (idx >= BB * 66 * 66) return;
    int cell = idx % 4356;
    int rr = cell / 66, cc = cell % 66;
    if (rr == 0 || rr == 65 || cc == 0 || cc == 65) {
        size_t o = (size_t)idx * 512;
        uint4 z = make_uint4(0, 0, 0, 0);
        #pragma unroll
        for (int k = 0; k < 64; ++k)
            *(uint4*)(g_xp + o + k * 8) = z;
    }
}

// ---------------- kernel 6: modulate + round + transpose input -> xp (fp16) ----------------
__global__ void __launch_bounds__(256)
k_xprep(const float* __restrict__ input) {
    __shared__ __align__(16) unsigned short sh[64 * 128];
    const int r = blockIdx.x, b = blockIdx.y, tid = threadIdx.x;
    const float scale = 0.014731391f;   // 1/sqrt(4608)
    for (int icb = 0; icb < CIN; icb += 128) {
        #pragma unroll
        for (int k = 0; k < 8; ++k) {
            int idx = tid + (k << 8);
            int icl = idx >> 4, c4 = idx & 15;
            int ic  = icb + icl;
            float s = scale * g_smod[b * CIN + ic];
            float4 v = *(const float4*)(input + ((size_t)(b * CIN + ic) * HH + r) * WW + (c4 << 2));
            float xs[4] = {v.x * s, v.y * s, v.z * s, v.w * s};
            #pragma unroll
            for (int j = 0; j < 4; ++j) {
                int c = (c4 << 2) + j;
                sh[c * 128 + icl] = __half_as_ushort(__float2half_rn(xs[j]));
            }
        }
        __syncthreads();
        #pragma unroll
        for (int k = 0; k < 2; ++k) {
            int q = tid + (k << 8);
            int c = q >> 3, kk = q & 7;
            size_t dst = (((size_t)b * 66 + r + 1) * 66 + c + 1) * 512 + icb + (kk << 4);
            *(uint4*)(g_xp + dst)     = *(const uint4*)(sh + c * 128 + (kk << 4));
            *(uint4*)(g_xp + dst + 8) = *(const uint4*)(sh + c * 128 + (kk << 4) + 8);
        }
        __syncthreads();
    }
}

// ---------------- kernel 7: warp-MMA implicit-GEMM conv (fp16, fat tile) ---------
// CTA: M=128 oc x N=256 px (4 rows). 8 warps (2x4), warp tile 64x64.
// K=128 per iteration (two 64-ic sub-chunks), 36 iterations total (9 taps x 4).
// 2-stage double buffer: stage = {W0 16K, W1 16K, X0 32K, X1 32K} = 96KB, 192KB smem.
__global__ void __launch_bounds__(256, 1)
k_conv_mma(float* __restrict__ out) {
    extern __shared__ char dsm[];
    const int tid = threadIdx.x, lane = tid & 31, wid = tid >> 5;
    const int wm = wid >> 2, wn = wid & 3;
    const int b = blockIdx.z, ocb = blockIdx.y << 7, rp = blockIdx.x;  // rp: 4-row group 0..15

    const uint32_t sb = (uint32_t)__cvta_generic_to_shared(dsm);
    const unsigned short* __restrict__ xb = g_xp + (size_t)b * 66 * 66 * 512;

    // ldmatrix row offsets (fixed per thread); rows are 128B in each sub-block
    uint32_t arow_off[4], brow_off[4];
    #pragma unroll
    for (int mi = 0; mi < 4; ++mi)
        arow_off[mi] = (uint32_t)((wm * 64 + mi * 16 + (lane & 15)) * 128);
    #pragma unroll
    for (int nj = 0; nj < 4; ++nj)
        brow_off[nj] = (uint32_t)((wn * 64 + nj * 16 + ((lane >> 4) << 3) + (lane & 7)) * 128);
    const uint32_t swz = (uint32_t)(lane & 7);

    float acc[4][8][4];
    #pragma unroll
    for (int mi = 0; mi < 4; ++mi)
        #pragma unroll
        for (int nt = 0; nt < 8; ++nt)
            #pragma unroll
            for (int k = 0; k < 4; ++k) acc[mi][nt][k] = 0.f;

    // stage layout: {W0:0, W1:16K, X0:32K, X1:64K}, 96KB per stage, 2 stages
    auto issue = [&](int it) {
        const int st = it & 1;
        const int t = it >> 2, icb2 = (it & 3) << 7;     // tap, 128-ic block
        const int dh = t / 3, dw = t - dh * 3;
        const uint32_t s0 = sb + (uint32_t)st * 98304u;
        #pragma unroll
        for (int sub = 0; sub < 2; ++sub) {
            const int icb = icb2 + (sub << 6);
            const uint32_t w0 = s0 + (uint32_t)sub * 16384u;
            const uint32_t x0 = s0 + 32768u + (uint32_t)sub * 32768u;
            #pragma unroll
            for (int k2 = 0; k2 < 4; ++k2) {             // W rows 0..127
                int q = tid + (k2 << 8);
                int row = q >> 3, cc = q & 7;
                uint32_t doff = (uint32_t)(row * 128 + (((uint32_t)cc ^ (uint32_t)(row & 7)) << 4));
                size_t wsrc = ((size_t)t * COUT + ocb + row) * CIN + icb + (cc << 3);
                cp16(w0 + doff, g_wp + wsrc);
            }
            #pragma unroll
            for (int k2 = 0; k2 < 8; ++k2) {             // X rows 0..255 (px)
                int q = tid + (k2 << 8);
                int row = q >> 3, cc = q & 7;
                uint32_t doff = (uint32_t)(row * 128 + (((uint32_t)cc ^ (uint32_t)(row & 7)) << 4));
                int pr = row >> 6, pc = row & 63;
                size_t xsrc = ((size_t)(rp * 4 + pr + dh) * 66 + (pc + dw)) * 512 + icb + (cc << 3);
                cp16(x0 + doff, xb + xsrc);
            }
        }
        cp_commit();
    };

    issue(0);
    for (int it = 0; it < 36; ++it) {
        if (it < 35) { issue(it + 1); cp_wait<1>(); }
        else         { cp_wait<0>(); }
        __syncthreads();

        const uint32_t s0 = sb + (uint32_t)(it & 1) * 98304u;
        #pragma unroll
        for (int sub = 0; sub < 2; ++sub) {
            const uint32_t w0 = s0 + (uint32_t)sub * 16384u;
            const uint32_t x0 = s0 + 32768u + (uint32_t)sub * 32768u;
            #pragma unroll
            for (int ks = 0; ks < 4; ++ks) {
                const uint32_t ca = (((uint32_t)(2 * ks) + (uint32_t)(lane >> 4)) ^ swz) << 4;
                const uint32_t cb = (((uint32_t)(2 * ks) + (uint32_t)((lane >> 3) & 1)) ^ swz) << 4;
                uint32_t Ah[4][4], Bh[4][4];
                #pragma unroll
                for (int mi = 0; mi < 4; ++mi)
                    LDSM4(Ah[mi], w0 + arow_off[mi] + ca);
                #pragma unroll
                for (int nj = 0; nj < 4; ++nj)
                    LDSM4(Bh[nj], x0 + brow_off[nj] + cb);
                #pragma unroll
                for (int mi = 0; mi < 4; ++mi)
                    #pragma unroll
                    for (int nt = 0; nt < 8; ++nt) {
                        const int nj = nt >> 1, hp = (nt & 1) << 1;
                        MMA(acc[mi][nt], Ah[mi], Bh[nj][hp], Bh[nj][hp + 1]);
                    }
            }
        }
        __syncthreads();
    }

    // -------- epilogue: demod scale + store --------
    const int r0c = lane >> 2, cp2 = (lane & 3) << 1;
    #pragma unroll
    for (int mi = 0; mi < 4; ++mi) {
        const int oc0 = ocb + wm * 64 + mi * 16 + r0c, oc1 = oc0 + 8;
        const float d0 = g_demod[b * COUT + oc0];
        const float d1 = g_demod[b * COUT + oc1];
        float* p0 = out + ((size_t)b * COUT + oc0) * 4096 + rp * 256;
        float* p1 = out + ((size_t)b * COUT + oc1) * 4096 + rp * 256;
        #pragma unroll
        for (int nt = 0; nt < 8; ++nt) {
            const int nc = wn * 64 + nt * 8 + cp2;
            float2 v0 = make_float2(acc[mi][nt][0] * d0, acc[mi][nt][1] * d0);
            float2 v1 = make_float2(acc[mi][nt][2] * d1, acc[mi][nt][3] * d1);
            *(float2*)(p0 + nc) = v0;
            *(float2*)(p1 + nc) = v1;
        }
    }
}

// ---------------- launch ----------------
extern "C" void kernel_launch(void* const* d_in, const int* in_sizes, int n_in,
                              void* d_out, int out_size) {
    const float* input  = (const float*)d_in[0];  // (16,512,64,64)
    const float* style  = (const float*)d_in[1];  // (16,512)
    const float* weight = (const float*)d_in[2];  // (512,512,3,3)
    const float* mod_w  = (const float*)d_in[3];  // (512,512)
    const float* mod_b  = (const float*)d_in[4];  // (512,)
    float* out = (float*)d_out;                   // (16,512,64,64)
    (void)in_sizes; (void)n_in; (void)out_size;

    k_mod   <<<1024, 256>>>(style, mod_w, mod_b);
    k_wsq   <<<1024, 256>>>(weight);
    k_demod <<<1024, 256>>>();
    k_wprep <<<1024, 256>>>(weight);
    k_border<<<(BB * 66 * 66 + 255) / 256, 256>>>();
    k_xprep <<<dim3(64, 16), 256>>>(input);

    cudaFuncSetAttribute(k_conv_mma, cudaFuncAttributeMaxDynamicSharedMemorySize, 196608);
    k_conv_mma<<<dim3(16, 4, 16), 256, 196608>>>(out);
}

// round 13
// speedup vs baseline: 11.8414x; 1.0086x over previous
#include <cuda_runtime.h>
#include <cuda_fp16.h>
#include <cstdint>

#define BB   16
#define CIN  512
#define COUT 512
#define HH   64
#define WW   64
#define SS   512

// ---------------- scratch (__device__ globals: allocation-free) ----------------
__device__ float g_smod[BB * CIN];      // s[b][i]
__device__ float g_demod[BB * COUT];    // demod[b][o]
__device__ float g_wsq[COUT * CIN];     // per-(o,i) 3x3 weight energy

// fp16 weights, [t][oc][ic]
__device__ __align__(16) unsigned short g_wp[9 * COUT * CIN];
// padded modulated input, channel-last [b][66][66][ic], fp16
__device__ __align__(16) unsigned short g_xp[35684352];

// ---------------- baseline-ISA helpers (sm_80-era: safe at .target sm_103) ----
__device__ __forceinline__ void cp16(uint32_t dst, const void* src) {
    asm volatile("cp.async.cg.shared.global [%0], [%1], 16;" :: "r"(dst), "l"(src) : "memory");
}
__device__ __forceinline__ void cp_commit() { asm volatile("cp.async.commit_group;" ::: "memory"); }
template <int N> __device__ __forceinline__ void cp_wait() {
    asm volatile("cp.async.wait_group %0;" :: "n"(N) : "memory");
}
#define LDSM4(r, addr) \
    asm volatile("ldmatrix.sync.aligned.m8n8.x4.shared.b16 {%0,%1,%2,%3}, [%4];" \
                 : "=r"((r)[0]), "=r"((r)[1]), "=r"((r)[2]), "=r"((r)[3]) : "r"(addr))
#define MMA(c, a, b0v, b1v) \
    asm volatile("mma.sync.aligned.m16n8k16.row.col.f32.f16.f16.f32 " \
                 "{%0,%1,%2,%3}, {%4,%5,%6,%7}, {%8,%9}, {%0,%1,%2,%3};" \
                 : "+f"((c)[0]), "+f"((c)[1]), "+f"((c)[2]), "+f"((c)[3]) \
                 : "r"((a)[0]), "r"((a)[1]), "r"((a)[2]), "r"((a)[3]), "r"(b0v), "r"(b1v))

// ---------------- kernel 1: s = style @ mod_w^T + mod_b ----------------
__global__ void k_mod(const float* __restrict__ style, const float* __restrict__ mod_w,
                      const float* __restrict__ mod_b) {
    int wid  = (blockIdx.x * blockDim.x + threadIdx.x) >> 5;
    int lane = threadIdx.x & 31;
    if (wid >= BB * CIN) return;
    int b = wid >> 9, i = wid & 511;
    const float* st = style + b * SS;
    const float* mw = mod_w + (size_t)i * SS;
    float sum = 0.f;
    for (int l = lane; l < SS; l += 32) sum += st[l] * mw[l];
    #pragma unroll
    for (int o = 16; o > 0; o >>= 1) sum += __shfl_xor_sync(0xffffffffu, sum, o);
    if (lane == 0) g_smod[wid] = sum + mod_b[i];
}

// ---------------- kernel 2: wsq ----------------
__global__ void k_wsq(const float* __restrict__ weight) {
    int idx = blockIdx.x * blockDim.x + threadIdx.x;
    if (idx >= COUT * CIN) return;
    const float* w = weight + (size_t)idx * 9;
    float s = 0.f;
    #pragma unroll
    for (int t = 0; t < 9; ++t) s += w[t] * w[t];
    g_wsq[idx] = s;
}

// ---------------- kernel 3: demod ----------------
__global__ void k_demod() {
    int wid  = (blockIdx.x * blockDim.x + threadIdx.x) >> 5;
    int lane = threadIdx.x & 31;
    if (wid >= BB * COUT) return;
    int b = wid >> 9, o = wid & 511;
    const float* wsq = g_wsq + (size_t)o * CIN;
    const float* sm  = g_smod + b * CIN;
    float sum = 0.f;
    for (int i = lane; i < CIN; i += 32) { float s = sm[i]; sum += wsq[i] * s * s; }
    #pragma unroll
    for (int off = 16; off > 0; off >>= 1) sum += __shfl_xor_sync(0xffffffffu, sum, off);
    const float scale2 = 2.1701389e-4f;   // 1/(Cin*K*K)
    if (lane == 0) g_demod[wid] = rsqrtf(scale2 * sum + 1e-8f);
}

// ---------------- kernel 4: weights -> [t][oc][ic] fp16 ----------------
__global__ void k_wprep(const float* __restrict__ weight) {
    int idx = blockIdx.x * 256 + threadIdx.x;
    if (idx >= COUT * CIN) return;
    int oc = idx >> 9, ic = idx & 511;
    const float* w = weight + (size_t)idx * 9;
    #pragma unroll
    for (int t = 0; t < 9; ++t) {
        size_t o = ((size_t)t * COUT + oc) * CIN + ic;
        g_wp[o] = __half_as_ushort(__float2half_rn(w[t]));
    }
}

// ---------------- kernel 5: zero pad border of xp ----------------
__global__ void k_border() {
    int idx = blockIdx.x * 256 + threadIdx.x;   // b*4356 + rr*66 + cc
    if (idx >= BB * 66 * 66) return;
    int cell = idx % 4356;
    int rr = cell / 66, cc = cell % 66;
    if (rr == 0 || rr == 65 || cc == 0 || cc == 65) {
        size_t o = (size_t)idx * 512;
        uint4 z = make_uint4(0, 0, 0, 0);
        #pragma unroll
        for (int k = 0; k < 64; ++k)
            *(uint4*)(g_xp + o + k * 8) = z;
    }
}

// ---------------- kernel 6: modulate + round + transpose input -> xp (fp16) ----------------
__global__ void __launch_bounds__(256)
k_xprep(const float* __restrict__ input) {
    __shared__ __align__(16) unsigned short sh[64 * 128];
    const int r = blockIdx.x, b = blockIdx.y, tid = threadIdx.x;
    const float scale = 0.014731391f;   // 1/sqrt(4608)
    for (int icb = 0; icb < CIN; icb += 128) {
        #pragma unroll
        for (int k = 0; k < 8; ++k) {
            int idx = tid + (k << 8);
            int icl = idx >> 4, c4 = idx & 15;
            int ic  = icb + icl;
            float s = scale * g_smod[b * CIN + ic];
            float4 v = *(const float4*)(input + ((size_t)(b * CIN + ic) * HH + r) * WW + (c4 << 2));
            float xs[4] = {v.x * s, v.y * s, v.z * s, v.w * s};
            #pragma unroll
            for (int j = 0; j < 4; ++j) {
                int c = (c4 << 2) + j;
                sh[c * 128 + icl] = __half_as_ushort(__float2half_rn(xs[j]));
            }
        }
        __syncthreads();
        #pragma unroll
        for (int k = 0; k < 2; ++k) {
            int q = tid + (k << 8);
            int c = q >> 3, kk = q & 7;
            size_t dst = (((size_t)b * 66 + r + 1) * 66 + c + 1) * 512 + icb + (kk << 4);
            *(uint4*)(g_xp + dst)     = *(const uint4*)(sh + c * 128 + (kk << 4));
            *(uint4*)(g_xp + dst + 8) = *(const uint4*)(sh + c * 128 + (kk << 4) + 8);
        }
        __syncthreads();
    }
}

// ---------------- kernel 7: warp-MMA implicit-GEMM conv, X-halo, 2 CTA/SM -------
// CTA: M=128 oc x N=128 px (2 rows). 8 warps (2x4), warp tile 64x32.
// Outer: 8 ic-blocks of 64. X halo (4x66 px-rows, 33.8KB) staged ONCE per ic-block;
// inner: 9 taps, each reads shifted windows from the halo. W: 3-slot ring (16KB),
// distance-2 cp.async prefetch, ONE sync per step. smem 81KB -> 2 CTAs/SM.
__global__ void __launch_bounds__(256, 2)
k_conv_mma(float* __restrict__ out) {
    extern __shared__ char dsm[];
    const int tid = threadIdx.x, lane = tid & 31, wid = tid >> 5;
    const int wm = wid >> 2, wn = wid & 3;
    const int b = blockIdx.z, ocb = blockIdx.y << 7, rp = blockIdx.x;  // rp: row-pair 0..31

    const uint32_t sb = (uint32_t)__cvta_generic_to_shared(dsm);
    const uint32_t xb = sb + 49152u;                       // X halo after 3x16KB W ring
    const unsigned short* __restrict__ xg = g_xp + (size_t)b * 66 * 66 * 512;

    // A (weights) ldmatrix offsets: row = wm*64 + mi*16 + (lane&15); row&7 == lane&7
    uint32_t arow_off[4];
    #pragma unroll
    for (int mi = 0; mi < 4; ++mi)
        arow_off[mi] = (uint32_t)((wm * 64 + mi * 16 + (lane & 15)) * 128);
    const uint32_t aswz = (uint32_t)(lane & 7);
    const uint32_t cpart = (uint32_t)((lane >> 3) & 1);
    const int prbase = wn >> 1;                             // image row within tile (0/1)
    const int pcbase = ((wn & 1) << 5) + (((lane >> 4) & 1) << 3) + (lane & 7);

    float acc[4][4][4];
    #pragma unroll
    for (int mi = 0; mi < 4; ++mi)
        #pragma unroll
        for (int nt = 0; nt < 4; ++nt)
            #pragma unroll
            for (int k = 0; k < 4; ++k) acc[mi][nt][k] = 0.f;

    // W panel stage: 128 rows x 64 ic (16KB), swizzled 128B rows; ring slot s%3
    auto issueW = [&](int s) {
        const int t = s % 9, icb = (s / 9) << 6;
        const uint32_t w0 = sb + (uint32_t)(s % 3) * 16384u;
        #pragma unroll
        for (int k2 = 0; k2 < 4; ++k2) {
            int q = tid + (k2 << 8);
            int row = q >> 3, cc = q & 7;
            uint32_t doff = (uint32_t)(row * 128 + (((uint32_t)cc ^ (uint32_t)(row & 7)) << 4));
            cp16(w0 + doff, g_wp + ((size_t)t * COUT + ocb + row) * CIN + icb + (cc << 3));
        }
    };
    // X halo stage: 4 padded rows x 66 cols x 64 ic = 264 rows of 128B (33792B)
    auto issueX = [&](int icb6) {
        for (int i = tid; i < 2112; i += 256) {
            int row = i >> 3, cc = i & 7;       // row = hr*66 + hc
            int hr = row / 66, hc = row - hr * 66;
            uint32_t doff = (uint32_t)(row * 128 + (((uint32_t)cc ^ (uint32_t)(row & 7)) << 4));
            cp16(xb + doff, xg + ((size_t)(rp * 2 + hr) * 66 + hc) * 512 + icb6 + (cc << 3));
        }
    };

    // prologue: G0 = {X halo(icb0), W(0)}, G1 = {W(1)}
    issueX(0); issueW(0); cp_commit();
    issueW(1); cp_commit();

    for (int s = 0; s < 72; ++s) {
        const int t = s % 9, icb = s / 9;
        cp_wait<1>();
        __syncthreads();
        if (t == 0 && icb > 0) {
            issueX(icb << 6);
            if (s + 2 < 72) issueW(s + 2);
            cp_commit();
            cp_wait<0>();
            __syncthreads();
        } else {
            if (s + 2 < 72) issueW(s + 2);
            cp_commit();                         // commit each step (empty ok) -> uniform counts
        }

        const uint32_t w0 = sb + (uint32_t)(s % 3) * 16384u;
        const int dh = t / 3, dw = t - dh * 3;
        // B rows for this tap: hrow = (prbase+dh)*66 + pcbase + dw  (nj=1: +16)
        const uint32_t h0 = (uint32_t)((prbase + dh) * 66 + pcbase + dw);
        const uint32_t h1 = h0 + 16;
        const uint32_t b0 = xb + h0 * 128, b1 = xb + h1 * 128;
        const uint32_t s70 = h0 & 7, s71 = h1 & 7;

        #pragma unroll
        for (int ks = 0; ks < 4; ++ks) {
            const uint32_t ca = (((uint32_t)(2 * ks) + (uint32_t)(lane >> 4)) ^ aswz) << 4;
            const uint32_t c0 = (((uint32_t)(2 * ks) + cpart) ^ s70) << 4;
            const uint32_t c1 = (((uint32_t)(2 * ks) + cpart) ^ s71) << 4;
            uint32_t Ah[4][4], Bh[2][4];
            #pragma unroll
            for (int mi = 0; mi < 4; ++mi)
                LDSM4(Ah[mi], w0 + arow_off[mi] + ca);
            LDSM4(Bh[0], b0 + c0);
            LDSM4(Bh[1], b1 + c1);
            #pragma unroll
            for (int mi = 0; mi < 4; ++mi)
                #pragma unroll
                for (int nt = 0; nt < 4; ++nt) {
                    const int nj = nt >> 1, hp = (nt & 1) << 1;
                    MMA(acc[mi][nt], Ah[mi], Bh[nj][hp], Bh[nj][hp + 1]);
                }
        }
        // no end-of-step sync: next step's (wait, sync) precedes any buffer write
    }

    // -------- epilogue: demod scale + store --------
    const int r0c = lane >> 2, cp2 = (lane & 3) << 1;
    #pragma unroll
    for (int mi = 0; mi < 4; ++mi) {
        const int oc0 = ocb + wm * 64 + mi * 16 + r0c, oc1 = oc0 + 8;
        const float d0 = g_demod[b * COUT + oc0];
        const float d1 = g_demod[b * COUT + oc1];
        float* p0 = out + ((size_t)b * COUT + oc0) * 4096 + rp * 128;
        float* p1 = out + ((size_t)b * COUT + oc1) * 4096 + rp * 128;
        #pragma unroll
        for (int nt = 0; nt < 4; ++nt) {
            const int nc = wn * 32 + nt * 8 + cp2;
            float2 v0 = make_float2(acc[mi][nt][0] * d0, acc[mi][nt][1] * d0);
            float2 v1 = make_float2(acc[mi][nt][2] * d1, acc[mi][nt][3] * d1);
            *(float2*)(p0 + nc) = v0;
            *(float2*)(p1 + nc) = v1;
        }
    }
}

// ---------------- launch ----------------
extern "C" void kernel_launch(void* const* d_in, const int* in_sizes, int n_in,
                              void* d_out, int out_size) {
    const float* input  = (const float*)d_in[0];  // (16,512,64,64)
    const float* style  = (const float*)d_in[1];  // (16,512)
    const float* weight = (const float*)d_in[2];  // (512,512,3,3)
    const float* mod_w  = (const float*)d_in[3];  // (512,512)
    const float* mod_b  = (const float*)d_in[4];  // (512,)
    float* out = (float*)d_out;                   // (16,512,64,64)
    (void)in_sizes; (void)n_in; (void)out_size;

    k_mod   <<<1024, 256>>>(style, mod_w, mod_b);
    k_wsq   <<<1024, 256>>>(weight);
    k_demod <<<1024, 256>>>();
    k_wprep <<<1024, 256>>>(weight);
    k_border<<<(BB * 66 * 66 + 255) / 256, 256>>>();
    k_xprep <<<dim3(64, 16), 256>>>(input);

    cudaFuncSetAttribute(k_conv_mma, cudaFuncAttributeMaxDynamicSharedMemorySize, 82944);
    k_conv_mma<<<dim3(32, 4, 16), 256, 82944>>>(out);
}

// round 14
// speedup vs baseline: 14.4998x; 1.2245x over previous
#include <cuda_runtime.h>
#include <cuda_fp16.h>
#include <cstdint>

#define BB   16
#define CIN  512
#define COUT 512
#define HH   64
#define WW   64
#define SS   512

// ---------------- scratch (__device__ globals: allocation-free) ----------------
__device__ float g_smod[BB * CIN];      // s[b][i]
__device__ float g_demod[BB * COUT];    // demod[b][o]
__device__ float g_wsq[COUT * CIN];     // per-(o,i) 3x3 weight energy

// Winograd transformed weights U[p][oc][ic], p = xi*4+nu, fp16 (8MB)
__device__ __align__(16) unsigned short g_u[16 * COUT * CIN];
// Winograd transformed input V[b*16+p][tile][ic], fp16 (256MB)
__device__ __align__(16) unsigned short g_v[268435456 / 2];
// GEMM output M[b*16+p][oc][tile], fp32 (512MB)
__device__ __align__(16) float g_m[134217728];

// ---------------- baseline-ISA helpers (sm_80-era: safe at .target sm_103) ----
__device__ __forceinline__ void cp16(uint32_t dst, const void* src) {
    asm volatile("cp.async.cg.shared.global [%0], [%1], 16;" :: "r"(dst), "l"(src) : "memory");
}
__device__ __forceinline__ void cp_commit() { asm volatile("cp.async.commit_group;" ::: "memory"); }
template <int N> __device__ __forceinline__ void cp_wait() {
    asm volatile("cp.async.wait_group %0;" :: "n"(N) : "memory");
}
#define LDSM4(r, addr) \
    asm volatile("ldmatrix.sync.aligned.m8n8.x4.shared.b16 {%0,%1,%2,%3}, [%4];" \
                 : "=r"((r)[0]), "=r"((r)[1]), "=r"((r)[2]), "=r"((r)[3]) : "r"(addr))
#define MMA(c, a, b0v, b1v) \
    asm volatile("mma.sync.aligned.m16n8k16.row.col.f32.f16.f16.f32 " \
                 "{%0,%1,%2,%3}, {%4,%5,%6,%7}, {%8,%9}, {%0,%1,%2,%3};" \
                 : "+f"((c)[0]), "+f"((c)[1]), "+f"((c)[2]), "+f"((c)[3]) \
                 : "r"((a)[0]), "r"((a)[1]), "r"((a)[2]), "r"((a)[3]), "r"(b0v), "r"(b1v))

// ---------------- kernel 1: s = style @ mod_w^T + mod_b ----------------
__global__ void k_mod(const float* __restrict__ style, const float* __restrict__ mod_w,
                      const float* __restrict__ mod_b) {
    int wid  = (blockIdx.x * blockDim.x + threadIdx.x) >> 5;
    int lane = threadIdx.x & 31;
    if (wid >= BB * CIN) return;
    int b = wid >> 9, i = wid & 511;
    const float* st = style + b * SS;
    const float* mw = mod_w + (size_t)i * SS;
    float sum = 0.f;
    for (int l = lane; l < SS; l += 32) sum += st[l] * mw[l];
    #pragma unroll
    for (int o = 16; o > 0; o >>= 1) sum += __shfl_xor_sync(0xffffffffu, sum, o);
    if (lane == 0) g_smod[wid] = sum + mod_b[i];
}

// ---------------- kernel 2: wsq ----------------
__global__ void k_wsq(const float* __restrict__ weight) {
    int idx = blockIdx.x * blockDim.x + threadIdx.x;
    if (idx >= COUT * CIN) return;
    const float* w = weight + (size_t)idx * 9;
    float s = 0.f;
    #pragma unroll
    for (int t = 0; t < 9; ++t) s += w[t] * w[t];
    g_wsq[idx] = s;
}

// ---------------- kernel 3: demod ----------------
__global__ void k_demod() {
    int wid  = (blockIdx.x * blockDim.x + threadIdx.x) >> 5;
    int lane = threadIdx.x & 31;
    if (wid >= BB * COUT) return;
    int b = wid >> 9, o = wid & 511;
    const float* wsq = g_wsq + (size_t)o * CIN;
    const float* sm  = g_smod + b * CIN;
    float sum = 0.f;
    for (int i = lane; i < CIN; i += 32) { float s = sm[i]; sum += wsq[i] * s * s; }
    #pragma unroll
    for (int off = 16; off > 0; off >>= 1) sum += __shfl_xor_sync(0xffffffffu, sum, off);
    const float scale2 = 2.1701389e-4f;   // 1/(Cin*K*K)
    if (lane == 0) g_demod[wid] = rsqrtf(scale2 * sum + 1e-8f);
}

// ---------------- kernel 4: Winograd weight transform U = G (scale*w) G^T -----
__global__ void k_uprep(const float* __restrict__ weight) {
    int idx = blockIdx.x * 256 + threadIdx.x;       // oc*512 + ic
    if (idx >= COUT * CIN) return;
    const float* w = weight + (size_t)idx * 9;
    const float sc = 0.014731391f;                   // 1/sqrt(4608)
    float g0[3], g1[3], g2[3];
    #pragma unroll
    for (int j = 0; j < 3; ++j) { g0[j] = w[j] * sc; g1[j] = w[3 + j] * sc; g2[j] = w[6 + j] * sc; }
    float t[4][3];
    #pragma unroll
    for (int j = 0; j < 3; ++j) {
        t[0][j] = g0[j];
        t[1][j] = 0.5f * (g0[j] + g1[j] + g2[j]);
        t[2][j] = 0.5f * (g0[j] - g1[j] + g2[j]);
        t[3][j] = g2[j];
    }
    #pragma unroll
    for (int i = 0; i < 4; ++i) {
        float u0 = t[i][0];
        float u1 = 0.5f * (t[i][0] + t[i][1] + t[i][2]);
        float u2 = 0.5f * (t[i][0] - t[i][1] + t[i][2]);
        float u3 = t[i][2];
        g_u[(size_t)(i * 4 + 0) * (COUT * CIN) + idx] = __half_as_ushort(__float2half_rn(u0));
        g_u[(size_t)(i * 4 + 1) * (COUT * CIN) + idx] = __half_as_ushort(__float2half_rn(u1));
        g_u[(size_t)(i * 4 + 2) * (COUT * CIN) + idx] = __half_as_ushort(__float2half_rn(u2));
        g_u[(size_t)(i * 4 + 3) * (COUT * CIN) + idx] = __half_as_ushort(__float2half_rn(u3));
    }
}

// ---------------- kernel 5: Winograd input transform V = B^T (s*d) B ----------
// Block = (ty, icb, b): stages 4 input rows x 66 cols x 64 ic into smem,
// computes V for 32 tiles x 64 ic, writes coalesced to g_v[b*16+p][tile][ic].
__global__ void __launch_bounds__(256)
k_vprep(const float* __restrict__ input) {
    extern __shared__ float sm[];
    float* sx = sm;                                            // [row*66+col][ic] (4*66*64 f32)
    __half2* vs = (__half2*)((char*)sm + 67584);               // [p][tx][icp] (16*32*32 half2)
    const int ty = blockIdx.x, icb = blockIdx.y, b = blockIdx.z;
    const int tid = threadIdx.x;

    // stage: thread = (ic, row)
    {
        int ic = tid & 63, row = tid >> 6;
        int icg = (icb << 6) + ic;
        float s = g_smod[b * CIN + icg];
        int gr = 2 * ty - 1 + row;
        float* dst = sx + (row * 66) * 64 + ic;
        if (gr >= 0 && gr < HH) {
            const float4* src = (const float4*)(input + ((size_t)(b * CIN + icg) * HH + gr) * WW);
            dst[0] = 0.f; dst[65 * 64] = 0.f;
            #pragma unroll
            for (int c4 = 0; c4 < 16; ++c4) {
                float4 v = src[c4];
                dst[(c4 * 4 + 1) * 64] = v.x * s;
                dst[(c4 * 4 + 2) * 64] = v.y * s;
                dst[(c4 * 4 + 3) * 64] = v.z * s;
                dst[(c4 * 4 + 4) * 64] = v.w * s;
            }
        } else {
            #pragma unroll
            for (int c = 0; c < 66; ++c) dst[c * 64] = 0.f;
        }
    }
    __syncthreads();

    // compute: thread = (icp 0..31, txg 0..7), 4 tiles each, 2 ics per thread
    {
        int icp = tid & 31, txg = tid >> 5;
        #pragma unroll
        for (int k = 0; k < 4; ++k) {
            int tx = txg + (k << 3);
            float dx[4][4], dy[4][4];
            #pragma unroll
            for (int r = 0; r < 4; ++r)
                #pragma unroll
                for (int c = 0; c < 4; ++c) {
                    float2 v = *(const float2*)(sx + ((r * 66) + (2 * tx + c)) * 64 + icp * 2);
                    dx[r][c] = v.x; dy[r][c] = v.y;
                }
            float txm[4][4], tym[4][4];
            #pragma unroll
            for (int j = 0; j < 4; ++j) {
                txm[0][j] = dx[0][j] - dx[2][j];  tym[0][j] = dy[0][j] - dy[2][j];
                txm[1][j] = dx[1][j] + dx[2][j];  tym[1][j] = dy[1][j] + dy[2][j];
                txm[2][j] = dx[2][j] - dx[1][j];  tym[2][j] = dy[2][j] - dy[1][j];
                txm[3][j] = dx[1][j] - dx[3][j];  tym[3][j] = dy[1][j] - dy[3][j];
            }
            #pragma unroll
            for (int i = 0; i < 4; ++i) {
                float vx0 = txm[i][0] - txm[i][2], vy0 = tym[i][0] - tym[i][2];
                float vx1 = txm[i][1] + txm[i][2], vy1 = tym[i][1] + tym[i][2];
                float vx2 = txm[i][2] - txm[i][1], vy2 = tym[i][2] - tym[i][1];
                float vx3 = txm[i][1] - txm[i][3], vy3 = tym[i][1] - tym[i][3];
                vs[((i * 4 + 0) * 32 + tx) * 32 + icp] = __floats2half2_rn(vx0, vy0);
                vs[((i * 4 + 1) * 32 + tx) * 32 + icp] = __floats2half2_rn(vx1, vy1);
                vs[((i * 4 + 2) * 32 + tx) * 32 + icp] = __floats2half2_rn(vx2, vy2);
                vs[((i * 4 + 3) * 32 + tx) * 32 + icp] = __floats2half2_rn(vx3, vy3);
            }
        }
    }
    __syncthreads();

    // writeback: 16 planes x 32 tiles x 64 ic halfs = 4096 uint4, coalesced
    {
        const uint4* vsrc = (const uint4*)vs;
        #pragma unroll
        for (int k = 0; k < 16; ++k) {
            int j = tid + (k << 8);
            int p = j >> 8, rem = j & 255, tx = rem >> 3, ch = rem & 7;
            uint4 val = vsrc[(p * 32 + tx) * 8 + ch];
            *(uint4*)(g_v + (((size_t)(b * 16 + p) * 1024 + ty * 32 + tx) * 512 + (icb << 6) + ch * 8)) = val;
        }
    }
}

// ---------------- kernel 6: batched GEMM M[gz] = U[p] x V[gz]^T --------------
// 256 GEMMs (gz = b*16+p) of [512 oc x 1024 tiles x 512 ic].
// CTA: 128 oc x 256 tiles, 8 warps (2x4), warp 64x64. K=64/iter, 8 iters,
// 3-stage cp.async ring (48KB/stage = 144KB).
__global__ void __launch_bounds__(256, 1)
k_gemm() {
    extern __shared__ char dsm[];
    const int tid = threadIdx.x, lane = tid & 31, wid = tid >> 5;
    const int wm = wid >> 2, wn = wid & 3;
    const int gz = blockIdx.z;                   // b*16 + p
    const int ocb = blockIdx.y << 7, nb = blockIdx.x << 8;

    const uint32_t sb = (uint32_t)__cvta_generic_to_shared(dsm);
    const unsigned short* __restrict__ ug = g_u + (size_t)(gz & 15) * (COUT * CIN);
    const unsigned short* __restrict__ vg = g_v + (size_t)gz * 1024 * 512;

    uint32_t arow_off[4], brow_off[4];
    #pragma unroll
    for (int mi = 0; mi < 4; ++mi)
        arow_off[mi] = (uint32_t)((wm * 64 + mi * 16 + (lane & 15)) * 128);
    #pragma unroll
    for (int nj = 0; nj < 4; ++nj)
        brow_off[nj] = (uint32_t)((wn * 64 + nj * 16 + ((lane >> 4) << 3) + (lane & 7)) * 128);
    const uint32_t swz = (uint32_t)(lane & 7);

    float acc[4][8][4];
    #pragma unroll
    for (int mi = 0; mi < 4; ++mi)
        #pragma unroll
        for (int nt = 0; nt < 8; ++nt)
            #pragma unroll
            for (int k = 0; k < 4; ++k) acc[mi][nt][k] = 0.f;

    // stage layout: {W:16KB, X:32KB} per slot, 3 slots
    auto issue = [&](int it) {
        const uint32_t s0 = sb + (uint32_t)(it % 3) * 49152u;
        const int icb = it << 6;
        #pragma unroll
        for (int k2 = 0; k2 < 4; ++k2) {
            int q = tid + (k2 << 8);
            int row = q >> 3, cc = q & 7;
            uint32_t doff = (uint32_t)(row * 128 + (((uint32_t)cc ^ (uint32_t)(row & 7)) << 4));
            cp16(s0 + doff, ug + ((size_t)(ocb + row)) * 512 + icb + (cc << 3));
        }
        #pragma unroll
        for (int k2 = 0; k2 < 8; ++k2) {
            int q = tid + (k2 << 8);
            int row = q >> 3, cc = q & 7;
            uint32_t doff = (uint32_t)(row * 128 + (((uint32_t)cc ^ (uint32_t)(row & 7)) << 4));
            cp16(s0 + 16384 + doff, vg + ((size_t)(nb + row)) * 512 + icb + (cc << 3));
        }
        cp_commit();
    };

    issue(0);
    issue(1);
    for (int it = 0; it < 8; ++it) {
        if (it < 6)      { issue(it + 2); cp_wait<2>(); }
        else if (it == 6){ cp_wait<1>(); }
        else             { cp_wait<0>(); }
        __syncthreads();

        const uint32_t s0 = sb + (uint32_t)(it % 3) * 49152u;
        const uint32_t w0 = s0, x0 = s0 + 16384u;
        #pragma unroll
        for (int ks = 0; ks < 4; ++ks) {
            const uint32_t ca = (((uint32_t)(2 * ks) + (uint32_t)(lane >> 4)) ^ swz) << 4;
            const uint32_t cb = (((uint32_t)(2 * ks) + (uint32_t)((lane >> 3) & 1)) ^ swz) << 4;
            uint32_t Ah[4][4], Bh[4][4];
            #pragma unroll
            for (int mi = 0; mi < 4; ++mi)
                LDSM4(Ah[mi], w0 + arow_off[mi] + ca);
            #pragma unroll
            for (int nj = 0; nj < 4; ++nj)
                LDSM4(Bh[nj], x0 + brow_off[nj] + cb);
            #pragma unroll
            for (int mi = 0; mi < 4; ++mi)
                #pragma unroll
                for (int nt = 0; nt < 8; ++nt) {
                    const int nj = nt >> 1, hp = (nt & 1) << 1;
                    MMA(acc[mi][nt], Ah[mi], Bh[nj][hp], Bh[nj][hp + 1]);
                }
        }
        __syncthreads();
    }

    // epilogue: store M fp32
    const int r0c = lane >> 2, cp2 = (lane & 3) << 1;
    float* mbase = g_m + (size_t)gz * 512 * 1024;
    #pragma unroll
    for (int mi = 0; mi < 4; ++mi) {
        const int oc0 = ocb + wm * 64 + mi * 16 + r0c, oc1 = oc0 + 8;
        float* p0 = mbase + (size_t)oc0 * 1024 + nb;
        float* p1 = mbase + (size_t)oc1 * 1024 + nb;
        #pragma unroll
        for (int nt = 0; nt < 8; ++nt) {
            const int nc = wn * 64 + nt * 8 + cp2;
            *(float2*)(p0 + nc) = make_float2(acc[mi][nt][0], acc[mi][nt][1]);
            *(float2*)(p1 + nc) = make_float2(acc[mi][nt][2], acc[mi][nt][3]);
        }
    }
}

// ---------------- kernel 7: output transform Y = A^T M A, demod, store -------
__global__ void __launch_bounds__(256)
k_ytrans(float* __restrict__ out) {
    const int blk = blockIdx.x;                  // b*512 + oc
    const int b = blk >> 9, oc = blk & 511;
    const float dm = g_demod[b * COUT + oc];
    const float* mb = g_m + ((size_t)(b * 16) * 512 + oc) * 1024;  // + p*524288 + tile
    float* ob = out + (size_t)blk * 4096;
    #pragma unroll
    for (int k = 0; k < 4; ++k) {
        int tile = threadIdx.x + (k << 8);
        int tty = tile >> 5, ttx = tile & 31;
        float m[4][4];
        #pragma unroll
        for (int p = 0; p < 16; ++p)
            m[p >> 2][p & 3] = mb[(size_t)p * 524288 + tile];
        float s0[4], s1[4];
        #pragma unroll
        for (int j = 0; j < 4; ++j) {
            s0[j] = m[0][j] + m[1][j] + m[2][j];
            s1[j] = m[1][j] - m[2][j] - m[3][j];
        }
        float y00 = (s0[0] + s0[1] + s0[2]) * dm;
        float y01 = (s0[1] - s0[2] - s0[3]) * dm;
        float y10 = (s1[0] + s1[1] + s1[2]) * dm;
        float y11 = (s1[1] - s1[2] - s1[3]) * dm;
        *(float2*)(ob + (2 * tty) * 64 + 2 * ttx)     = make_float2(y00, y01);
        *(float2*)(ob + (2 * tty + 1) * 64 + 2 * ttx) = make_float2(y10, y11);
    }
}

// ---------------- launch ----------------
extern "C" void kernel_launch(void* const* d_in, const int* in_sizes, int n_in,
                              void* d_out, int out_size) {
    const float* input  = (const float*)d_in[0];  // (16,512,64,64)
    const float* style  = (const float*)d_in[1];  // (16,512)
    const float* weight = (const float*)d_in[2];  // (512,512,3,3)
    const float* mod_w  = (const float*)d_in[3];  // (512,512)
    const float* mod_b  = (const float*)d_in[4];  // (512,)
    float* out = (float*)d_out;                   // (16,512,64,64)
    (void)in_sizes; (void)n_in; (void)out_size;

    k_mod   <<<1024, 256>>>(style, mod_w, mod_b);
    k_wsq   <<<1024, 256>>>(weight);
    k_demod <<<1024, 256>>>();
    k_uprep <<<1024, 256>>>(weight);

    cudaFuncSetAttribute(k_vprep, cudaFuncAttributeMaxDynamicSharedMemorySize, 133120);
    k_vprep<<<dim3(32, 8, 16), 256, 133120>>>(input);

    cudaFuncSetAttribute(k_gemm, cudaFuncAttributeMaxDynamicSharedMemorySize, 147456);
    k_gemm<<<dim3(4, 4, 256), 256, 147456>>>();

    k_ytrans<<<BB * COUT, 256>>>(out);
}